// round 10
// baseline (speedup 1.0000x reference)
#include <cuda_runtime.h>
#include <cuda_fp16.h>
#include <cstdint>

#define Nn 32768
#define Dd 256
#define Kk 8192

#define BM 128
#define BN 128
#define BK 32
#define NCHUNK (Kk / BN)        // 64
#define NIT (NCHUNK * 8)        // 512 iterations
#define NSTAGE 5
#define CAPL 16384u
#define CAPH 8192u
#define MARGIN 0.05f
#define KSPLIT 8

// ---------------------------------------------------------------------------
// Device scratch
// ---------------------------------------------------------------------------
__device__ __half g_xh[Nn * Dd];
__device__ __half g_wh[Kk * Dd];
__device__ float g_wn[Kk];
__device__ int g_idx[Nn];
__device__ int g_cand[Nn * 8];
__device__ unsigned int g_lflag[CAPL];
__device__ unsigned int g_hflag[CAPH];
__device__ unsigned int g_nl;
__device__ unsigned int g_nh;
__device__ unsigned long long g_res[Nn];

// ---------------------------------------------------------------------------
__device__ __forceinline__ uint32_t smem_to_u32(const void* p) {
    uint32_t a;
    asm("{ .reg .u64 t; cvta.to.shared.u64 t, %1; cvt.u32.u64 %0, t; }"
        : "=r"(a) : "l"(p));
    return a;
}

__device__ __forceinline__ void cpasync16(uint32_t dst, const void* src) {
    asm volatile("cp.async.cg.shared.global [%0], [%1], 16;" :: "r"(dst), "l"(src));
}

#define CP_COMMIT() asm volatile("cp.async.commit_group;" ::: "memory")
#define CP_WAIT3()  asm volatile("cp.async.wait_group 3;" ::: "memory")

#define LDSM_X4(r0, r1, r2, r3, addr) \
    asm volatile("ldmatrix.sync.aligned.m8n8.x4.shared.b16 {%0,%1,%2,%3}, [%4];" \
        : "=r"(r0), "=r"(r1), "=r"(r2), "=r"(r3) : "r"(addr))

#define MMA16816(c, a, b) \
    asm volatile("mma.sync.aligned.m16n8k16.row.col.f32.f16.f16.f32 " \
        "{%0,%1,%2,%3}, {%4,%5,%6,%7}, {%8,%9}, {%0,%1,%2,%3};" \
        : "+f"((c)[0]), "+f"((c)[1]), "+f"((c)[2]), "+f"((c)[3]) \
        : "r"((a)[0]), "r"((a)[1]), "r"((a)[2]), "r"((a)[3]), \
          "r"((b)[0]), "r"((b)[1]))

__device__ __forceinline__ unsigned long long pack_key(float s, int k) {
    unsigned u = __float_as_uint(s);
    u = (u & 0x80000000u) ? ~u : (u | 0x80000000u);
    return ((unsigned long long)u << 32) | (unsigned long long)(0xFFFFFFFFu - (unsigned)k);
}

// SMEM layout (stage1, dynamic), 80B row pitch:
#define SM_STAGE  20480
#define ATILE 0
#define BTILE 10240
#define SM_WNS    102400
#define SM_MV1    103424
#define SM_MV2    107520
#define SM_MI     111616
#define SMEM_TOTAL 115712

// ---------------------------------------------------------------------------
// Preprocessing
// ---------------------------------------------------------------------------
__global__ void convx_kernel(const float* __restrict__ X) {
    int i = blockIdx.x * 256 + threadIdx.x;
    if (i == 0) { g_nl = 0; g_nh = 0; }
    if (i < Nn * Dd / 2) {
        float2 v = ((const float2*)X)[i];
        ((__half2*)g_xh)[i] = __halves2half2(__float2half(v.x), __float2half(v.y));
    }
}

__global__ void convw_kernel(const float* __restrict__ W) {
    int i = blockIdx.x * 256 + threadIdx.x;
    if (i < Kk * Dd / 2) {
        float2 v = ((const float2*)W)[i];
        ((__half2*)g_wh)[i] = __halves2half2(__float2half(v.x), __float2half(v.y));
    }
}

__global__ void wnorm_kernel(const float* __restrict__ W) {
    int k = blockIdx.x * 8 + (threadIdx.x >> 5);
    int lane = threadIdx.x & 31;
    const float4* wp = (const float4*)(W + (size_t)k * Dd);
    float4 a = wp[lane * 2];
    float4 b = wp[lane * 2 + 1];
    float s = a.x * a.x + a.y * a.y + a.z * a.z + a.w * a.w
            + b.x * b.x + b.y * b.y + b.z * b.z + b.w * b.w;
    #pragma unroll
    for (int o = 16; o > 0; o >>= 1) s += __shfl_xor_sync(0xffffffffu, s, o);
    if (lane == 0) g_wn[k] = 0.5f * s;
}

// ---------------------------------------------------------------------------
// Stage 1: fp16 warp-MMA GEMM, 5-stage cp.async pipeline, 2 CTAs/SM
// ---------------------------------------------------------------------------
__global__ void __launch_bounds__(256, 2) stage1_kernel() {
    extern __shared__ char smem[];
    const uint32_t sbase = smem_to_u32(smem);
    float* wnsS = (float*)(smem + SM_WNS);
    float* mv1 = (float*)(smem + SM_MV1);
    float* mv2 = (float*)(smem + SM_MV2);
    int*   mi  = (int*)(smem + SM_MI);

    const int tid = threadIdx.x;
    const int lane = tid & 31;
    const int wid = tid >> 5;
    const int warp_m = wid & 3;
    const int warp_n = wid >> 2;
    const int row0 = blockIdx.x * BM;

    const uint32_t aBase = sbase + ATILE +
        (uint32_t)((warp_m * 32 + (lane & 15)) * 80 + (lane >> 4) * 16);
    const uint32_t bBase = sbase + BTILE +
        (uint32_t)((warp_n * 64 + (lane & 7) + ((lane >> 4) & 1) * 8) * 80 +
                   ((lane >> 3) & 1) * 16);

    const int ldRow = tid >> 1;
    const int ldC0 = (tid & 1) * 2;

    #pragma unroll
    for (int p = 0; p < 4; p++) {
        const uint32_t st = sbase + (uint32_t)(p * SM_STAGE);
        #pragma unroll
        for (int q = 0; q < 2; q++) {
            int c = ldC0 + q;
            cpasync16(st + ATILE + (uint32_t)(ldRow * 80 + c * 16),
                      g_xh + (size_t)(row0 + ldRow) * Dd + p * BK + c * 8);
            cpasync16(st + BTILE + (uint32_t)(ldRow * 80 + c * 16),
                      g_wh + (size_t)ldRow * Dd + p * BK + c * 8);
        }
        CP_COMMIT();
    }
    if (tid < BN) wnsS[tid] = g_wn[tid];

    float best1[4], best2[4];
    int idx1[4];
    #pragma unroll
    for (int r = 0; r < 4; r++) { best1[r] = -3.4e38f; best2[r] = -3.4e38f; idx1[r] = 0; }

    float acc[2][8][4];

    int cur = 0;
    int fill = 4;

    for (int it = 0; it < NIT; it++) {
        const int ch = it >> 3;
        const int kt = it & 7;

        CP_WAIT3();
        __syncthreads();

        {
            int nit = it + 4; if (nit >= NIT) nit -= NIT;
            const int nch = nit >> 3;
            const int nkt = nit & 7;
            const uint32_t st = sbase + (uint32_t)(fill * SM_STAGE);
            #pragma unroll
            for (int q = 0; q < 2; q++) {
                int c = ldC0 + q;
                cpasync16(st + ATILE + (uint32_t)(ldRow * 80 + c * 16),
                          g_xh + (size_t)(row0 + ldRow) * Dd + nkt * BK + c * 8);
                cpasync16(st + BTILE + (uint32_t)(ldRow * 80 + c * 16),
                          g_wh + (size_t)(nch * BN + ldRow) * Dd + nkt * BK + c * 8);
            }
            CP_COMMIT();
        }

        if (kt == 0) {
            #pragma unroll
            for (int i = 0; i < 2; i++)
                #pragma unroll
                for (int j = 0; j < 8; j++)
                    #pragma unroll
                    for (int q = 0; q < 4; q++) acc[i][j][q] = 0.0f;
            if (ch + 1 < NCHUNK && tid < BN)
                wnsS[((ch + 1) & 1) * BN + tid] = g_wn[(ch + 1) * BN + tid];
        }

        const uint32_t so = (uint32_t)(cur * SM_STAGE);
        #pragma unroll
        for (int ks = 0; ks < 2; ks++) {
            uint32_t a[2][4];
            #pragma unroll
            for (int i = 0; i < 2; i++)
                LDSM_X4(a[i][0], a[i][1], a[i][2], a[i][3],
                        aBase + so + (uint32_t)(i * 1280 + ks * 32));
            uint32_t b[8][2];
            #pragma unroll
            for (int jp = 0; jp < 4; jp++)
                LDSM_X4(b[2 * jp][0], b[2 * jp][1], b[2 * jp + 1][0], b[2 * jp + 1][1],
                        bBase + so + (uint32_t)(jp * 1280 + ks * 32));
            #pragma unroll
            for (int i = 0; i < 2; i++)
                #pragma unroll
                for (int j = 0; j < 8; j++)
                    MMA16816(acc[i][j], a[i], b[j]);
        }

        if (++cur == NSTAGE) cur = 0;
        if (++fill == NSTAGE) fill = 0;

        if (kt == 7) {
            const int kc = ch * BN;
            const float* wn = wnsS + (ch & 1) * BN;
            #pragma unroll
            for (int i = 0; i < 2; i++) {
                #pragma unroll
                for (int h = 0; h < 2; h++) {
                    const int r = i * 2 + h;
                    #pragma unroll
                    for (int j = 0; j < 8; j++) {
                        int col = warp_n * 64 + j * 8 + (lane & 3) * 2;
                        #pragma unroll
                        for (int q = 0; q < 2; q++) {
                            float s = acc[i][j][h * 2 + q] - wn[col + q];
                            int k = kc + col + q;
                            if (s > best1[r]) { best2[r] = best1[r]; best1[r] = s; idx1[r] = k; }
                            else if (s > best2[r]) { best2[r] = s; }
                        }
                    }
                }
            }
        }
    }

    // cross-thread merge: 8 entries per row (disjoint column ranges per entry)
    const int e = warp_n * 4 + (lane & 3);
    #pragma unroll
    for (int r = 0; r < 4; r++) {
        int row = warp_m * 32 + (r >> 1) * 16 + (lane >> 2) + (r & 1) * 8;
        mv1[row * 8 + e] = best1[r];
        mv2[row * 8 + e] = best2[r];
        mi[row * 8 + e] = idx1[r];
    }
    __syncthreads();

    if (tid < BM) {
        float b1 = -3.4e38f;
        int bi = 0;
        #pragma unroll
        for (int t = 0; t < 8; t++) {
            float v = mv1[tid * 8 + t];
            int ii = mi[tid * 8 + t];
            if (v > b1 || (v == b1 && ii < bi)) { b1 = v; bi = ii; }
        }
        int n = row0 + tid;
        g_idx[n] = bi;

        const float thr = b1 - MARGIN;
        int cands[8];
        int ncand = 0;
        bool heavy = false;
        #pragma unroll
        for (int t = 0; t < 8; t++) {
            if (mv1[tid * 8 + t] >= thr) cands[ncand++] = mi[tid * 8 + t];
            if (mv2[tid * 8 + t] >= thr) heavy = true;
        }

        if (heavy) {
            unsigned slot = atomicAdd(&g_nh, 1u);
            if (slot < CAPH) {
                g_res[n] = 0ull;
                __threadfence();
                g_hflag[slot] = n;
            }
        } else if (ncand >= 2) {
            unsigned slot = atomicAdd(&g_nl, 1u);
            if (slot < CAPL) {
                #pragma unroll
                for (int c = 0; c < 8; c++)
                    g_cand[n * 8 + c] = cands[c < ncand ? c : 0];
                __threadfence();
                g_lflag[slot] = n;
            }
        }
    }
}

// ---------------------------------------------------------------------------
// Light rescue: one warp per flagged row; exact fp32 rescore of <=8 candidates
// ---------------------------------------------------------------------------
__global__ void __launch_bounds__(256) light_kernel(const float* __restrict__ X,
                                                    const float* __restrict__ W) {
    unsigned cnt = g_nl; if (cnt > CAPL) cnt = CAPL;
    unsigned r = blockIdx.x * 8 + (threadIdx.x >> 5);
    if (r >= cnt) return;
    const int lane = threadIdx.x & 31;
    const int n = (int)g_lflag[r];

    const float4* xp = (const float4*)(X + (size_t)n * Dd);
    float4 x0 = xp[lane * 2];
    float4 x1 = xp[lane * 2 + 1];

    unsigned long long best = 0ull;
    #pragma unroll
    for (int c = 0; c < 8; c++) {
        int k = g_cand[n * 8 + c];
        const float4* wp = (const float4*)(W + (size_t)k * Dd);
        float4 w0 = wp[lane * 2];
        float4 w1 = wp[lane * 2 + 1];
        float dot = x0.x * w0.x + x0.y * w0.y + x0.z * w0.z + x0.w * w0.w
                  + x1.x * w1.x + x1.y * w1.y + x1.z * w1.z + x1.w * w1.w;
        #pragma unroll
        for (int o = 16; o > 0; o >>= 1) dot += __shfl_xor_sync(0xffffffffu, dot, o);
        float s = dot - g_wn[k];
        unsigned long long key = pack_key(s, k);
        if (key > best) best = key;
    }
    if (lane == 0)
        g_idx[n] = (int)(0xFFFFFFFFu - (unsigned)(best & 0xFFFFFFFFull));
}

// ---------------------------------------------------------------------------
// Heavy rescue: 64 rows/block x 1024-codeword K-split, exact fp32, atomicMax
// ---------------------------------------------------------------------------
#define WPITCH 260
#define RROWS 64
#define RS_XS 0
#define RS_WS (RROWS * 256 * 4)
#define RS_SMEM (RS_WS + 32 * WPITCH * 4)   // 98816 bytes

__global__ void __launch_bounds__(256) heavy_kernel(const float* __restrict__ X,
                                                    const float* __restrict__ W) {
    extern __shared__ char rsm[];
    float* xs = (float*)(rsm + RS_XS);
    float* ws = (float*)(rsm + RS_WS);

    unsigned cnt = g_nh; if (cnt > CAPH) cnt = CAPH;
    const unsigned grp = blockIdx.x >> 3;
    const int ksp = blockIdx.x & 7;
    if (grp * RROWS >= cnt) return;

    const int tid = threadIdx.x;
    const int w = tid >> 5;
    const int tx = tid & 31;

    #pragma unroll
    for (int q = 0; q < 16; q++) {
        int f = q * 256 + tid;
        int r = f >> 6, seg = f & 63;
        unsigned slot = grp * RROWS + r;
        int n = (int)g_hflag[slot < cnt ? slot : (grp * RROWS)];
        *(float4*)&xs[r * 256 + seg * 4] =
            ((const float4*)(X + (size_t)n * Dd))[seg];
    }

    unsigned long long key[8];
    #pragma unroll
    for (int i = 0; i < 8; i++) key[i] = 0ull;

    const int k0 = ksp * (Kk / KSPLIT);
    for (int kc = 0; kc < Kk / KSPLIT; kc += 32) {
        __syncthreads();
        {
            const int kr = tid >> 3, seg = tid & 7;
            const float4* src = (const float4*)(W + (size_t)(k0 + kc + kr) * Dd);
            #pragma unroll
            for (int q = 0; q < 8; q++)
                *(float4*)&ws[kr * WPITCH + (seg * 8 + q) * 4] = src[seg * 8 + q];
        }
        __syncthreads();

        const int k = k0 + kc + tx;
        float dot[8];
        #pragma unroll
        for (int i = 0; i < 8; i++) dot[i] = 0.0f;
        #pragma unroll
        for (int d = 0; d < 256; d += 4) {
            float4 wv = *(const float4*)&ws[tx * WPITCH + d];
            #pragma unroll
            for (int i = 0; i < 8; i++) {
                float4 xv = *(const float4*)&xs[(w * 8 + i) * 256 + d];
                dot[i] += wv.x * xv.x + wv.y * xv.y + wv.z * xv.z + wv.w * xv.w;
            }
        }
        const float wn = g_wn[k];
        #pragma unroll
        for (int i = 0; i < 8; i++) {
            unsigned long long kk2 = pack_key(dot[i] - wn, k);
            if (kk2 > key[i]) key[i] = kk2;
        }
    }

    #pragma unroll
    for (int i = 0; i < 8; i++) {
        unsigned long long kv = key[i];
        #pragma unroll
        for (int o = 16; o > 0; o >>= 1) {
            unsigned long long other = __shfl_xor_sync(0xffffffffu, kv, o);
            if (other > kv) kv = other;
        }
        if (tx == 0) {
            unsigned slot = grp * RROWS + w * 8 + i;
            if (slot < cnt) atomicMax(&g_res[g_hflag[slot]], kv);
        }
    }
}

__global__ void apply_kernel() {
    unsigned cnt = g_nh; if (cnt > CAPH) cnt = CAPH;
    unsigned t = blockIdx.x * 256 + threadIdx.x;
    if (t < cnt) {
        int n = (int)g_hflag[t];
        unsigned long long key = g_res[n];
        g_idx[n] = (int)(0xFFFFFFFFu - (unsigned)(key & 0xFFFFFFFFull));
    }
}

// ---------------------------------------------------------------------------
__global__ void gather_kernel(const float* __restrict__ W,
                              float* __restrict__ outq,
                              float* __restrict__ outi,
                              int write_idx) {
    int n = blockIdx.x;
    int idx = g_idx[n];
    const float4* src = (const float4*)(W + (size_t)idx * Dd);
    float4* dst = (float4*)(outq + (size_t)n * Dd);
    dst[threadIdx.x] = src[threadIdx.x];
    if (threadIdx.x == 0 && write_idx) outi[n] = (float)idx;
}

// ---------------------------------------------------------------------------
extern "C" void kernel_launch(void* const* d_in, const int* in_sizes, int n_in,
                              void* d_out, int out_size) {
    const float* X = (const float*)d_in[0];
    const float* W = (const float*)d_in[1];
    float* out = (float*)d_out;

    cudaFuncSetAttribute(stage1_kernel,
                         cudaFuncAttributeMaxDynamicSharedMemorySize, SMEM_TOTAL);
    cudaFuncSetAttribute(heavy_kernel,
                         cudaFuncAttributeMaxDynamicSharedMemorySize, RS_SMEM);

    convx_kernel<<<(Nn * Dd / 2 + 255) / 256, 256>>>(X);
    convw_kernel<<<(Kk * Dd / 2 + 255) / 256, 256>>>(W);
    wnorm_kernel<<<Kk / 8, 256>>>(W);

    stage1_kernel<<<Nn / BM, 256, SMEM_TOTAL>>>();

    light_kernel<<<CAPL / 8, 256>>>(X, W);
    heavy_kernel<<<(CAPH / RROWS) * KSPLIT, 256, RS_SMEM>>>(X, W);
    apply_kernel<<<(CAPH + 255) / 256, 256>>>();

    int write_idx = (out_size >= Nn * Dd + Nn) ? 1 : 0;
    gather_kernel<<<Nn, 64>>>(W, out, out + (size_t)Nn * Dd, write_idx);
}

// round 11
// speedup vs baseline: 1.0377x; 1.0377x over previous
#include <cuda_runtime.h>
#include <cuda_fp16.h>
#include <cstdint>

#define Nn 32768
#define Dd 256
#define Kk 8192

#define BM 128
#define BN 64
#define BK 32
#define NSPLIT 4
#define KSEG (Kk / NSPLIT)          // 2048 codewords per CTA
#define NCHUNK (KSEG / BN)          // 32 chunks
#define NIT (NCHUNK * 8)            // 256 iterations
#define CAPH 8192u
#define MARGIN 0.05f
#define KSPLIT 8

// ---------------------------------------------------------------------------
// Device scratch
// ---------------------------------------------------------------------------
__device__ __half g_xh[Nn * Dd];
__device__ __half g_wh[Kk * Dd];
__device__ float g_wn[Kk];
__device__ int g_idx[Nn];
__device__ float g_pb1[Nn * NSPLIT];
__device__ float g_pb2[Nn * NSPLIT];
__device__ int   g_pidx[Nn * NSPLIT];
__device__ unsigned int g_hflag[CAPH];
__device__ unsigned int g_nh;
__device__ unsigned long long g_res[Nn];

// ---------------------------------------------------------------------------
__device__ __forceinline__ uint32_t smem_to_u32(const void* p) {
    uint32_t a;
    asm("{ .reg .u64 t; cvta.to.shared.u64 t, %1; cvt.u32.u64 %0, t; }"
        : "=r"(a) : "l"(p));
    return a;
}

__device__ __forceinline__ void cpasync16(uint32_t dst, const void* src) {
    asm volatile("cp.async.cg.shared.global [%0], [%1], 16;" :: "r"(dst), "l"(src));
}

#define CP_COMMIT() asm volatile("cp.async.commit_group;" ::: "memory")
#define CP_WAIT2()  asm volatile("cp.async.wait_group 2;" ::: "memory")

#define LDSM_X4(r0, r1, r2, r3, addr) \
    asm volatile("ldmatrix.sync.aligned.m8n8.x4.shared.b16 {%0,%1,%2,%3}, [%4];" \
        : "=r"(r0), "=r"(r1), "=r"(r2), "=r"(r3) : "r"(addr))

#define MMA16816(c, a, b) \
    asm volatile("mma.sync.aligned.m16n8k16.row.col.f32.f16.f16.f32 " \
        "{%0,%1,%2,%3}, {%4,%5,%6,%7}, {%8,%9}, {%0,%1,%2,%3};" \
        : "+f"((c)[0]), "+f"((c)[1]), "+f"((c)[2]), "+f"((c)[3]) \
        : "r"((a)[0]), "r"((a)[1]), "r"((a)[2]), "r"((a)[3]), \
          "r"((b)[0]), "r"((b)[1]))

__device__ __forceinline__ unsigned long long pack_key(float s, int k) {
    unsigned u = __float_as_uint(s);
    u = (u & 0x80000000u) ? ~u : (u | 0x80000000u);
    return ((unsigned long long)u << 32) | (unsigned long long)(0xFFFFFFFFu - (unsigned)k);
}

// SMEM layout (stage1, dynamic), 80B pitch:
//  4 stages x (A 128x80 + B 64x80) = 4 x 15360 = 61440
//  wns[2][64] = 512 ; merge mv1/mv2 (128x8 f32) + mi (128x8 int)
#define SM_STAGE  15360
#define ATILE 0
#define BTILE 10240
#define SM_WNS    61440
#define SM_MV1    61952
#define SM_MV2    66048
#define SM_MI     70144
#define SMEM_TOTAL 74240

// ---------------------------------------------------------------------------
// Preprocessing
// ---------------------------------------------------------------------------
__global__ void convx_kernel(const float* __restrict__ X) {
    int i = blockIdx.x * 256 + threadIdx.x;
    if (i == 0) g_nh = 0;
    if (i < Nn * Dd / 2) {
        float2 v = ((const float2*)X)[i];
        ((__half2*)g_xh)[i] = __halves2half2(__float2half(v.x), __float2half(v.y));
    }
}

__global__ void convw_kernel(const float* __restrict__ W) {
    int i = blockIdx.x * 256 + threadIdx.x;
    if (i < Kk * Dd / 2) {
        float2 v = ((const float2*)W)[i];
        ((__half2*)g_wh)[i] = __halves2half2(__float2half(v.x), __float2half(v.y));
    }
}

__global__ void wnorm_kernel(const float* __restrict__ W) {
    int k = blockIdx.x * 8 + (threadIdx.x >> 5);
    int lane = threadIdx.x & 31;
    const float4* wp = (const float4*)(W + (size_t)k * Dd);
    float4 a = wp[lane * 2];
    float4 b = wp[lane * 2 + 1];
    float s = a.x * a.x + a.y * a.y + a.z * a.z + a.w * a.w
            + b.x * b.x + b.y * b.y + b.z * b.z + b.w * b.w;
    #pragma unroll
    for (int o = 16; o > 0; o >>= 1) s += __shfl_xor_sync(0xffffffffu, s, o);
    if (lane == 0) g_wn[k] = 0.5f * s;
}

// ---------------------------------------------------------------------------
// Stage 1: fp16 warp-MMA GEMM, CTA = 128 rows x 2048 codewords (K-split 4),
// warp tile 32x32, 4-stage cp.async pipeline, 3 CTAs/SM.
// ---------------------------------------------------------------------------
__global__ void __launch_bounds__(256, 3) stage1_kernel() {
    extern __shared__ char smem[];
    const uint32_t sbase = smem_to_u32(smem);
    float* wnsS = (float*)(smem + SM_WNS);
    float* mv1 = (float*)(smem + SM_MV1);
    float* mv2 = (float*)(smem + SM_MV2);
    int*   mi  = (int*)(smem + SM_MI);

    const int tid = threadIdx.x;
    const int lane = tid & 31;
    const int wid = tid >> 5;
    const int warp_m = wid & 3;        // 4 warps x 32 rows
    const int warp_n = wid >> 2;       // 2 warps x 32 cols
    const int row0 = (blockIdx.x >> 2) * BM;
    const int split = blockIdx.x & 3;
    const int k0 = split * KSEG;

    const uint32_t aBase = sbase + ATILE +
        (uint32_t)((warp_m * 32 + (lane & 15)) * 80 + (lane >> 4) * 16);
    const uint32_t bBase = sbase + BTILE +
        (uint32_t)((warp_n * 32 + (lane & 7) + ((lane >> 4) & 1) * 8) * 80 +
                   ((lane >> 3) & 1) * 16);

    // cp.async assignments per stage:
    //  A: 128 rows x 4 chunks: thread t -> row t>>1, chunks (t&1)*2, +1
    //  B:  64 rows x 4 chunks: thread t -> row t>>2, chunk t&3
    const int aRow = tid >> 1;
    const int aC0 = (tid & 1) * 2;
    const int bRow = tid >> 2;
    const int bC = tid & 3;

    // prologue: fill stages 0..2 (iters 0..2 = ch0, kt 0..2) + wns(ch0)
    #pragma unroll
    for (int p = 0; p < 3; p++) {
        const uint32_t st = sbase + (uint32_t)(p * SM_STAGE);
        cpasync16(st + ATILE + (uint32_t)(aRow * 80 + aC0 * 16),
                  g_xh + (size_t)(row0 + aRow) * Dd + p * BK + aC0 * 8);
        cpasync16(st + ATILE + (uint32_t)(aRow * 80 + (aC0 + 1) * 16),
                  g_xh + (size_t)(row0 + aRow) * Dd + p * BK + (aC0 + 1) * 8);
        cpasync16(st + BTILE + (uint32_t)(bRow * 80 + bC * 16),
                  g_wh + (size_t)(k0 + bRow) * Dd + p * BK + bC * 8);
        CP_COMMIT();
    }
    if (tid < BN) wnsS[tid] = g_wn[k0 + tid];

    float best1[4], best2[4];
    int idx1[4];
    #pragma unroll
    for (int r = 0; r < 4; r++) { best1[r] = -3.4e38f; best2[r] = -3.4e38f; idx1[r] = 0; }

    float acc[2][4][4];

    for (int it = 0; it < NIT; it++) {
        const int ch = it >> 3;
        const int kt = it & 7;

        CP_WAIT2();
        __syncthreads();

        // prefetch iter it+3 into stage (it+3)&3 (wrap at tail: harmless dummy)
        {
            int nit = it + 3; if (nit >= NIT) nit -= NIT;
            const int nch = nit >> 3;
            const int nkt = nit & 7;
            const uint32_t st = sbase + (uint32_t)(((it + 3) & 3) * SM_STAGE);
            cpasync16(st + ATILE + (uint32_t)(aRow * 80 + aC0 * 16),
                      g_xh + (size_t)(row0 + aRow) * Dd + nkt * BK + aC0 * 8);
            cpasync16(st + ATILE + (uint32_t)(aRow * 80 + (aC0 + 1) * 16),
                      g_xh + (size_t)(row0 + aRow) * Dd + nkt * BK + (aC0 + 1) * 8);
            cpasync16(st + BTILE + (uint32_t)(bRow * 80 + bC * 16),
                      g_wh + (size_t)(k0 + nch * BN + bRow) * Dd + nkt * BK + bC * 8);
            CP_COMMIT();
        }

        if (kt == 0) {
            #pragma unroll
            for (int i = 0; i < 2; i++)
                #pragma unroll
                for (int j = 0; j < 4; j++)
                    #pragma unroll
                    for (int q = 0; q < 4; q++) acc[i][j][q] = 0.0f;
            if (ch + 1 < NCHUNK && tid < BN)
                wnsS[((ch + 1) & 1) * BN + tid] = g_wn[k0 + (ch + 1) * BN + tid];
        }

        // compute: 2 k16-steps of warp tile 32x32
        const uint32_t so = (uint32_t)((it & 3) * SM_STAGE);
        #pragma unroll
        for (int ks = 0; ks < 2; ks++) {
            uint32_t a[2][4];
            #pragma unroll
            for (int i = 0; i < 2; i++)
                LDSM_X4(a[i][0], a[i][1], a[i][2], a[i][3],
                        aBase + so + (uint32_t)(i * 1280 + ks * 32));
            uint32_t b[4][2];
            #pragma unroll
            for (int jp = 0; jp < 2; jp++)
                LDSM_X4(b[2 * jp][0], b[2 * jp][1], b[2 * jp + 1][0], b[2 * jp + 1][1],
                        bBase + so + (uint32_t)(jp * 1280 + ks * 32));
            #pragma unroll
            for (int i = 0; i < 2; i++)
                #pragma unroll
                for (int j = 0; j < 4; j++)
                    MMA16816(acc[i][j], a[i], b[j]);
        }

        // fused top-2 argmax at chunk end
        if (kt == 7) {
            const int kc = k0 + ch * BN;
            const float* wn = wnsS + (ch & 1) * BN;
            #pragma unroll
            for (int i = 0; i < 2; i++) {
                #pragma unroll
                for (int h = 0; h < 2; h++) {
                    const int r = i * 2 + h;
                    #pragma unroll
                    for (int j = 0; j < 4; j++) {
                        int col = warp_n * 32 + j * 8 + (lane & 3) * 2;
                        #pragma unroll
                        for (int q = 0; q < 2; q++) {
                            float s = acc[i][j][h * 2 + q] - wn[col + q];
                            int k = kc + col + q;
                            if (s > best1[r]) { best2[r] = best1[r]; best1[r] = s; idx1[r] = k; }
                            else if (s > best2[r]) { best2[r] = s; }
                        }
                    }
                }
            }
        }
    }

    // cross-thread merge: 8 entries per row (warp_n x lane&3)
    const int e = warp_n * 4 + (lane & 3);
    #pragma unroll
    for (int r = 0; r < 4; r++) {
        int row = warp_m * 32 + (r >> 1) * 16 + (lane >> 2) + (r & 1) * 8;
        mv1[row * 8 + e] = best1[r];
        mv2[row * 8 + e] = best2[r];
        mi[row * 8 + e] = idx1[r];
    }
    __syncthreads();

    if (tid < BM) {
        float b1 = -3.4e38f, b2 = -3.4e38f;
        int bi = 0;
        #pragma unroll
        for (int t = 0; t < 8; t++) {
            float v = mv1[tid * 8 + t];
            int ii = mi[tid * 8 + t];
            if (v > b1 || (v == b1 && ii < bi)) { b2 = (b2 > b1) ? b2 : b1; b1 = v; bi = ii; }
            else if (v > b2) b2 = v;
            float v2 = mv2[tid * 8 + t];
            if (v2 > b2) b2 = v2;
        }
        int n = row0 + tid;
        g_pb1[n * NSPLIT + split] = b1;
        g_pb2[n * NSPLIT + split] = b2;
        g_pidx[n * NSPLIT + split] = bi;
    }
}

// ---------------------------------------------------------------------------
// Merge partials across 4 K-splits; write g_idx; flag margin rows
// ---------------------------------------------------------------------------
__global__ void merge_kernel() {
    int n = blockIdx.x * 256 + threadIdx.x;
    float b1 = -3.4e38f, b2 = -3.4e38f;
    int bi = 0;
    #pragma unroll
    for (int s = 0; s < NSPLIT; s++) {
        float v = g_pb1[n * NSPLIT + s];
        int ii = g_pidx[n * NSPLIT + s];
        float v2 = g_pb2[n * NSPLIT + s];
        if (v > b1 || (v == b1 && ii < bi)) { b2 = (b2 > b1) ? b2 : b1; b1 = v; bi = ii; }
        else if (v > b2) b2 = v;
        if (v2 > b2) b2 = v2;
    }
    g_idx[n] = bi;
    if (b1 - b2 < MARGIN) {
        unsigned slot = atomicAdd(&g_nh, 1u);
        if (slot < CAPH) {
            g_res[n] = 0ull;
            __threadfence();
            g_hflag[slot] = n;
        }
    }
}

// ---------------------------------------------------------------------------
// Heavy rescue: 64 rows/block x 1024-codeword K-split, exact fp32, atomicMax
// ---------------------------------------------------------------------------
#define WPITCH 260
#define RROWS 64
#define RS_XS 0
#define RS_WS (RROWS * 256 * 4)
#define RS_SMEM (RS_WS + 32 * WPITCH * 4)   // 98816 bytes

__global__ void __launch_bounds__(256) heavy_kernel(const float* __restrict__ X,
                                                    const float* __restrict__ W) {
    extern __shared__ char rsm[];
    float* xs = (float*)(rsm + RS_XS);
    float* ws = (float*)(rsm + RS_WS);

    unsigned cnt = g_nh; if (cnt > CAPH) cnt = CAPH;
    const unsigned grp = blockIdx.x >> 3;
    const int ksp = blockIdx.x & 7;
    if (grp * RROWS >= cnt) return;

    const int tid = threadIdx.x;
    const int w = tid >> 5;
    const int tx = tid & 31;

    #pragma unroll
    for (int q = 0; q < 16; q++) {
        int f = q * 256 + tid;
        int r = f >> 6, seg = f & 63;
        unsigned slot = grp * RROWS + r;
        int n = (int)g_hflag[slot < cnt ? slot : (grp * RROWS)];
        *(float4*)&xs[r * 256 + seg * 4] =
            ((const float4*)(X + (size_t)n * Dd))[seg];
    }

    unsigned long long key[8];
    #pragma unroll
    for (int i = 0; i < 8; i++) key[i] = 0ull;

    const int k0 = ksp * (Kk / KSPLIT);
    for (int kc = 0; kc < Kk / KSPLIT; kc += 32) {
        __syncthreads();
        {
            const int kr = tid >> 3, seg = tid & 7;
            const float4* src = (const float4*)(W + (size_t)(k0 + kc + kr) * Dd);
            #pragma unroll
            for (int q = 0; q < 8; q++)
                *(float4*)&ws[kr * WPITCH + (seg * 8 + q) * 4] = src[seg * 8 + q];
        }
        __syncthreads();

        const int k = k0 + kc + tx;
        float dot[8];
        #pragma unroll
        for (int i = 0; i < 8; i++) dot[i] = 0.0f;
        #pragma unroll
        for (int d = 0; d < 256; d += 4) {
            float4 wv = *(const float4*)&ws[tx * WPITCH + d];
            #pragma unroll
            for (int i = 0; i < 8; i++) {
                float4 xv = *(const float4*)&xs[(w * 8 + i) * 256 + d];
                dot[i] += wv.x * xv.x + wv.y * xv.y + wv.z * xv.z + wv.w * xv.w;
            }
        }
        const float wn = g_wn[k];
        #pragma unroll
        for (int i = 0; i < 8; i++) {
            unsigned long long kk2 = pack_key(dot[i] - wn, k);
            if (kk2 > key[i]) key[i] = kk2;
        }
    }

    #pragma unroll
    for (int i = 0; i < 8; i++) {
        unsigned long long kv = key[i];
        #pragma unroll
        for (int o = 16; o > 0; o >>= 1) {
            unsigned long long other = __shfl_xor_sync(0xffffffffu, kv, o);
            if (other > kv) kv = other;
        }
        if (tx == 0) {
            unsigned slot = grp * RROWS + w * 8 + i;
            if (slot < cnt) atomicMax(&g_res[g_hflag[slot]], kv);
        }
    }
}

__global__ void apply_kernel() {
    unsigned cnt = g_nh; if (cnt > CAPH) cnt = CAPH;
    unsigned t = blockIdx.x * 256 + threadIdx.x;
    if (t < cnt) {
        int n = (int)g_hflag[t];
        unsigned long long key = g_res[n];
        g_idx[n] = (int)(0xFFFFFFFFu - (unsigned)(key & 0xFFFFFFFFull));
    }
}

// ---------------------------------------------------------------------------
__global__ void gather_kernel(const float* __restrict__ W,
                              float* __restrict__ outq,
                              float* __restrict__ outi,
                              int write_idx) {
    int n = blockIdx.x;
    int idx = g_idx[n];
    const float4* src = (const float4*)(W + (size_t)idx * Dd);
    float4* dst = (float4*)(outq + (size_t)n * Dd);
    dst[threadIdx.x] = src[threadIdx.x];
    if (threadIdx.x == 0 && write_idx) outi[n] = (float)idx;
}

// ---------------------------------------------------------------------------
extern "C" void kernel_launch(void* const* d_in, const int* in_sizes, int n_in,
                              void* d_out, int out_size) {
    const float* X = (const float*)d_in[0];
    const float* W = (const float*)d_in[1];
    float* out = (float*)d_out;

    cudaFuncSetAttribute(stage1_kernel,
                         cudaFuncAttributeMaxDynamicSharedMemorySize, SMEM_TOTAL);
    cudaFuncSetAttribute(heavy_kernel,
                         cudaFuncAttributeMaxDynamicSharedMemorySize, RS_SMEM);

    convx_kernel<<<(Nn * Dd / 2 + 255) / 256, 256>>>(X);
    convw_kernel<<<(Kk * Dd / 2 + 255) / 256, 256>>>(W);
    wnorm_kernel<<<Kk / 8, 256>>>(W);

    stage1_kernel<<<(Nn / BM) * NSPLIT, 256, SMEM_TOTAL>>>();
    merge_kernel<<<Nn / 256, 256>>>();

    heavy_kernel<<<(CAPH / RROWS) * KSPLIT, 256, RS_SMEM>>>(X, W);
    apply_kernel<<<(CAPH + 255) / 256, 256>>>();

    int write_idx = (out_size >= Nn * Dd + Nn) ? 1 : 0;
    gather_kernel<<<Nn, 64>>>(W, out, out + (size_t)Nn * Dd, write_idx);
}

// round 14
// speedup vs baseline: 1.1192x; 1.0786x over previous
#include <cuda_runtime.h>
#include <cuda_fp16.h>
#include <cstdint>

#define Nn 32768
#define Dd 256
#define Kk 8192

#define BM 128
#define BN 64
#define BK 32
#define NSPLIT 4
#define KSEG (Kk / NSPLIT)          // 2048 codewords per CTA
#define NCHUNK (KSEG / BN)          // 32 chunks
#define CAPH 8192u
#define MARGIN 0.05f
#define KSPLIT 8

// ---------------------------------------------------------------------------
// Device scratch
// ---------------------------------------------------------------------------
__device__ __half g_xh[Nn * Dd];
__device__ __half g_wh[Kk * Dd];
__device__ float g_wn[Kk];
__device__ int g_idx[Nn];
__device__ float g_pb1[Nn * NSPLIT];
__device__ float g_pb2[Nn * NSPLIT];
__device__ int   g_pidx[Nn * NSPLIT];
__device__ unsigned int g_hflag[CAPH];
__device__ unsigned int g_nh;
__device__ unsigned long long g_res[Nn];

// ---------------------------------------------------------------------------
__device__ __forceinline__ uint32_t smem_to_u32(const void* p) {
    uint32_t a;
    asm("{ .reg .u64 t; cvta.to.shared.u64 t, %1; cvt.u32.u64 %0, t; }"
        : "=r"(a) : "l"(p));
    return a;
}

__device__ __forceinline__ void cpasync16(uint32_t dst, const void* src) {
    asm volatile("cp.async.cg.shared.global [%0], [%1], 16;" :: "r"(dst), "l"(src));
}

#define CP_COMMIT() asm volatile("cp.async.commit_group;" ::: "memory")
#define CP_WAIT2()  asm volatile("cp.async.wait_group 2;" ::: "memory")

#define LDSM_X4(r0, r1, r2, r3, addr) \
    asm volatile("ldmatrix.sync.aligned.m8n8.x4.shared.b16 {%0,%1,%2,%3}, [%4];" \
        : "=r"(r0), "=r"(r1), "=r"(r2), "=r"(r3) : "r"(addr))

#define MMA16816(c, a, b) \
    asm volatile("mma.sync.aligned.m16n8k16.row.col.f32.f16.f16.f32 " \
        "{%0,%1,%2,%3}, {%4,%5,%6,%7}, {%8,%9}, {%0,%1,%2,%3};" \
        : "+f"((c)[0]), "+f"((c)[1]), "+f"((c)[2]), "+f"((c)[3]) \
        : "r"((a)[0]), "r"((a)[1]), "r"((a)[2]), "r"((a)[3]), \
          "r"((b)[0]), "r"((b)[1]))

__device__ __forceinline__ unsigned long long pack_key(float s, int k) {
    unsigned u = __float_as_uint(s);
    u = (u & 0x80000000u) ? ~u : (u | 0x80000000u);
    return ((unsigned long long)u << 32) | (unsigned long long)(0xFFFFFFFFu - (unsigned)k);
}

// SMEM layout (stage1, dynamic), 80B pitch:
//  4 stages x (A 128x80 + B 64x80) = 4 x 15360 = 61440
//  wns[2][64] = 512 ; merge mv1/mv2 (128x8 f32) + mi
#define SM_STAGE  15360
#define ATILE 0
#define BTILE 10240
#define SM_WNS    61440
#define SM_MV1    61952
#define SM_MV2    66048
#define SM_MI     70144
#define SMEM_TOTAL 74240

// ---------------------------------------------------------------------------
// Fused preprocessing: convx | convw | wnorm by block range
//   X: Nn*Dd/2 float2 = 4194304 -> 16384 blocks
//   W: Kk*Dd/2 float2 = 1048576 ->  4096 blocks
//   wnorm: Kk/8 = 1024 blocks
// ---------------------------------------------------------------------------
#define CVX_BLKS 16384
#define CVW_BLKS 4096
#define WN_BLKS  1024

__global__ void prep_kernel(const float* __restrict__ X, const float* __restrict__ W) {
    int b = blockIdx.x;
    if (b == 0 && threadIdx.x == 0) g_nh = 0;
    if (b < CVX_BLKS) {
        int i = b * 256 + threadIdx.x;
        float2 v = ((const float2*)X)[i];
        ((__half2*)g_xh)[i] = __halves2half2(__float2half(v.x), __float2half(v.y));
    } else if (b < CVX_BLKS + CVW_BLKS) {
        int i = (b - CVX_BLKS) * 256 + threadIdx.x;
        float2 v = ((const float2*)W)[i];
        ((__half2*)g_wh)[i] = __halves2half2(__float2half(v.x), __float2half(v.y));
    } else {
        int k = (b - CVX_BLKS - CVW_BLKS) * 8 + (threadIdx.x >> 5);
        int lane = threadIdx.x & 31;
        const float4* wp = (const float4*)(W + (size_t)k * Dd);
        float4 a = wp[lane * 2];
        float4 c = wp[lane * 2 + 1];
        float s = a.x * a.x + a.y * a.y + a.z * a.z + a.w * a.w
                + c.x * c.x + c.y * c.y + c.z * c.z + c.w * c.w;
        #pragma unroll
        for (int o = 16; o > 0; o >>= 1) s += __shfl_xor_sync(0xffffffffu, s, o);
        if (lane == 0) g_wn[k] = 0.5f * s;
    }
}

// ---------------------------------------------------------------------------
// Stage 1: fp16 warp-MMA GEMM, CTA = 128 rows x 2048 codewords (K-split 4),
// warp tile 32x32, 4-stage pipeline with incremental bookkeeping, 3 CTAs/SM.
// ---------------------------------------------------------------------------
__global__ void __launch_bounds__(256, 3) stage1_kernel() {
    extern __shared__ char smem[];
    const uint32_t sbase = smem_to_u32(smem);
    float* wnsS = (float*)(smem + SM_WNS);
    float* mv1 = (float*)(smem + SM_MV1);
    float* mv2 = (float*)(smem + SM_MV2);
    int*   mi  = (int*)(smem + SM_MI);

    const int tid = threadIdx.x;
    const int lane = tid & 31;
    const int wid = tid >> 5;
    const int warp_m = wid & 3;
    const int warp_n = wid >> 2;
    const int row0 = (blockIdx.x >> 2) * BM;
    const int split = blockIdx.x & 3;
    const int k0 = split * KSEG;

    // lane-constant LDSM offsets (added to rotating stage base)
    const uint32_t laneA = (uint32_t)(ATILE +
        (warp_m * 32 + (lane & 15)) * 80 + (lane >> 4) * 16);
    const uint32_t laneB = (uint32_t)(BTILE +
        (warp_n * 32 + (lane & 7) + ((lane >> 4) & 1) * 8) * 80 +
        ((lane >> 3) & 1) * 16);

    // cp.async per-thread slots
    const int aRow = tid >> 1;
    const int aC0 = (tid & 1) * 2;
    const int bRow = tid >> 2;
    const int bC = tid & 3;
    const uint32_t aDst = (uint32_t)(ATILE + aRow * 80 + aC0 * 16);
    const uint32_t bDst = (uint32_t)(BTILE + bRow * 80 + bC * 16);

    // rotating stage bases (registers)
    uint32_t s0 = sbase;
    uint32_t s1 = sbase + SM_STAGE;
    uint32_t s2 = sbase + 2 * SM_STAGE;
    uint32_t s3 = sbase + 3 * SM_STAGE;

    // prologue: fill stages 0..2 with iters 0..2 (ch0, kt0..2)
    // NOTE: adjacent 16B chunk = +16 bytes smem, +8 halfs gmem.
    {
        const __half* aS = g_xh + (size_t)(row0 + aRow) * Dd + aC0 * 8;
        const __half* bS = g_wh + (size_t)(k0 + bRow) * Dd + bC * 8;
        uint32_t st[3] = { s0, s1, s2 };
        #pragma unroll
        for (int p = 0; p < 3; p++) {
            cpasync16(st[p] + aDst, aS + p * BK);
            cpasync16(st[p] + aDst + 16, aS + p * BK + 8);
            cpasync16(st[p] + bDst, bS + p * BK);
            CP_COMMIT();
        }
    }
    if (tid < BN) wnsS[tid] = g_wn[k0 + tid];

    // incremental prefetch state: next prefetch = iter 3 (ch 0, kt 3)
    const __half* aPref = g_xh + (size_t)(row0 + aRow) * Dd + aC0 * 8 + 3 * BK;
    const __half* bPref = g_wh + (size_t)(k0 + bRow) * Dd + bC * 8 + 3 * BK;
    int pkt = 3, pch = 0;

    float best1[4], best2[4];
    int idx1[4];
    #pragma unroll
    for (int r = 0; r < 4; r++) { best1[r] = -3.4e38f; best2[r] = -3.4e38f; idx1[r] = 0; }

    for (int ch = 0; ch < NCHUNK; ch++) {
        float acc[2][4][4];
        #pragma unroll
        for (int i = 0; i < 2; i++)
            #pragma unroll
            for (int j = 0; j < 4; j++)
                #pragma unroll
                for (int q = 0; q < 4; q++) acc[i][j][q] = 0.0f;

        #pragma unroll
        for (int kt = 0; kt < 8; kt++) {
            CP_WAIT2();
            __syncthreads();

            // next-chunk wns load (after the sync: previous epilogue readers done)
            if (kt == 0 && ch + 1 < NCHUNK && tid < BN)
                wnsS[((ch + 1) & 1) * BN + tid] = g_wn[k0 + (ch + 1) * BN + tid];

            // prefetch into s3 (iter it+3), pointers advance incrementally
            cpasync16(s3 + aDst, aPref);
            cpasync16(s3 + aDst + 16, aPref + 8);
            cpasync16(s3 + bDst, bPref);
            CP_COMMIT();
            if (++pkt == 8) {
                pkt = 0;
                aPref -= 7 * BK;
                bPref += BN * Dd - 7 * BK;
                if (++pch == NCHUNK) { pch = 0; bPref -= (size_t)KSEG * Dd; }
            } else {
                aPref += BK;
                bPref += BK;
            }

            // compute on s0: 2 k16-steps of warp tile 32x32
            #pragma unroll
            for (int ks = 0; ks < 2; ks++) {
                uint32_t a[2][4];
                #pragma unroll
                for (int i = 0; i < 2; i++)
                    LDSM_X4(a[i][0], a[i][1], a[i][2], a[i][3],
                            s0 + laneA + (uint32_t)(i * 1280 + ks * 32));
                uint32_t b[4][2];
                LDSM_X4(b[0][0], b[0][1], b[1][0], b[1][1],
                        s0 + laneB + (uint32_t)(ks * 32));
                LDSM_X4(b[2][0], b[2][1], b[3][0], b[3][1],
                        s0 + laneB + (uint32_t)(1280 + ks * 32));
                #pragma unroll
                for (int i = 0; i < 2; i++)
                    #pragma unroll
                    for (int j = 0; j < 4; j++)
                        MMA16816(acc[i][j], a[i], b[j]);
            }

            // rotate stages
            uint32_t t = s0; s0 = s1; s1 = s2; s2 = s3; s3 = t;
        }

        // fused top-2 argmax epilogue for this chunk
        const int kc = k0 + ch * BN;
        const float* wn = wnsS + (ch & 1) * BN;
        #pragma unroll
        for (int i = 0; i < 2; i++) {
            #pragma unroll
            for (int h = 0; h < 2; h++) {
                const int r = i * 2 + h;
                #pragma unroll
                for (int j = 0; j < 4; j++) {
                    int col = warp_n * 32 + j * 8 + (lane & 3) * 2;
                    #pragma unroll
                    for (int q = 0; q < 2; q++) {
                        float s = acc[i][j][h * 2 + q] - wn[col + q];
                        int k = kc + col + q;
                        if (s > best1[r]) { best2[r] = best1[r]; best1[r] = s; idx1[r] = k; }
                        else if (s > best2[r]) { best2[r] = s; }
                    }
                }
            }
        }
    }

    // cross-thread merge: 8 entries per row
    const int e = warp_n * 4 + (lane & 3);
    #pragma unroll
    for (int r = 0; r < 4; r++) {
        int row = warp_m * 32 + (r >> 1) * 16 + (lane >> 2) + (r & 1) * 8;
        mv1[row * 8 + e] = best1[r];
        mv2[row * 8 + e] = best2[r];
        mi[row * 8 + e] = idx1[r];
    }
    __syncthreads();

    if (tid < BM) {
        float b1 = -3.4e38f, b2 = -3.4e38f;
        int bi = 0;
        #pragma unroll
        for (int t = 0; t < 8; t++) {
            float v = mv1[tid * 8 + t];
            int ii = mi[tid * 8 + t];
            if (v > b1 || (v == b1 && ii < bi)) { b2 = (b2 > b1) ? b2 : b1; b1 = v; bi = ii; }
            else if (v > b2) b2 = v;
            float v2 = mv2[tid * 8 + t];
            if (v2 > b2) b2 = v2;
        }
        int n = row0 + tid;
        g_pb1[n * NSPLIT + split] = b1;
        g_pb2[n * NSPLIT + split] = b2;
        g_pidx[n * NSPLIT + split] = bi;
    }
}

// ---------------------------------------------------------------------------
// Merge partials across 4 K-splits; write g_idx; flag margin rows
// ---------------------------------------------------------------------------
__global__ void merge_kernel() {
    int n = blockIdx.x * 256 + threadIdx.x;
    float b1 = -3.4e38f, b2 = -3.4e38f;
    int bi = 0;
    #pragma unroll
    for (int s = 0; s < NSPLIT; s++) {
        float v = g_pb1[n * NSPLIT + s];
        int ii = g_pidx[n * NSPLIT + s];
        float v2 = g_pb2[n * NSPLIT + s];
        if (v > b1 || (v == b1 && ii < bi)) { b2 = (b2 > b1) ? b2 : b1; b1 = v; bi = ii; }
        else if (v > b2) b2 = v;
        if (v2 > b2) b2 = v2;
    }
    g_idx[n] = bi;
    if (b1 - b2 < MARGIN) {
        unsigned slot = atomicAdd(&g_nh, 1u);
        if (slot < CAPH) {
            g_res[n] = 0ull;
            __threadfence();
            g_hflag[slot] = n;
        }
    }
}

// ---------------------------------------------------------------------------
// Heavy rescue: 64 rows/block x 1024-codeword K-split, exact fp32, atomicMax
// ---------------------------------------------------------------------------
#define WPITCH 260
#define RROWS 64
#define RS_XS 0
#define RS_WS (RROWS * 256 * 4)
#define RS_SMEM (RS_WS + 32 * WPITCH * 4)   // 98816 bytes

__global__ void __launch_bounds__(256) heavy_kernel(const float* __restrict__ X,
                                                    const float* __restrict__ W) {
    extern __shared__ char rsm[];
    float* xs = (float*)(rsm + RS_XS);
    float* ws = (float*)(rsm + RS_WS);

    unsigned cnt = g_nh; if (cnt > CAPH) cnt = CAPH;
    const unsigned grp = blockIdx.x >> 3;
    const int ksp = blockIdx.x & 7;
    if (grp * RROWS >= cnt) return;

    const int tid = threadIdx.x;
    const int w = tid >> 5;
    const int tx = tid & 31;

    #pragma unroll
    for (int q = 0; q < 16; q++) {
        int f = q * 256 + tid;
        int r = f >> 6, seg = f & 63;
        unsigned slot = grp * RROWS + r;
        int n = (int)g_hflag[slot < cnt ? slot : (grp * RROWS)];
        *(float4*)&xs[r * 256 + seg * 4] =
            ((const float4*)(X + (size_t)n * Dd))[seg];
    }

    unsigned long long key[8];
    #pragma unroll
    for (int i = 0; i < 8; i++) key[i] = 0ull;

    const int k0 = ksp * (Kk / KSPLIT);
    for (int kc = 0; kc < Kk / KSPLIT; kc += 32) {
        __syncthreads();
        {
            const int kr = tid >> 3, seg = tid & 7;
            const float4* src = (const float4*)(W + (size_t)(k0 + kc + kr) * Dd);
            #pragma unroll
            for (int q = 0; q < 8; q++)
                *(float4*)&ws[kr * WPITCH + (seg * 8 + q) * 4] = src[seg * 8 + q];
        }
        __syncthreads();

        const int k = k0 + kc + tx;
        float dot[8];
        #pragma unroll
        for (int i = 0; i < 8; i++) dot[i] = 0.0f;
        #pragma unroll
        for (int d = 0; d < 256; d += 4) {
            float4 wv = *(const float4*)&ws[tx * WPITCH + d];
            #pragma unroll
            for (int i = 0; i < 8; i++) {
                float4 xv = *(const float4*)&xs[(w * 8 + i) * 256 + d];
                dot[i] += wv.x * xv.x + wv.y * xv.y + wv.z * xv.z + wv.w * xv.w;
            }
        }
        const float wn = g_wn[k];
        #pragma unroll
        for (int i = 0; i < 8; i++) {
            unsigned long long kk2 = pack_key(dot[i] - wn, k);
            if (kk2 > key[i]) key[i] = kk2;
        }
    }

    #pragma unroll
    for (int i = 0; i < 8; i++) {
        unsigned long long kv = key[i];
        #pragma unroll
        for (int o = 16; o > 0; o >>= 1) {
            unsigned long long other = __shfl_xor_sync(0xffffffffu, kv, o);
            if (other > kv) kv = other;
        }
        if (tx == 0) {
            unsigned slot = grp * RROWS + w * 8 + i;
            if (slot < cnt) atomicMax(&g_res[g_hflag[slot]], kv);
        }
    }
}

__global__ void apply_kernel() {
    unsigned cnt = g_nh; if (cnt > CAPH) cnt = CAPH;
    unsigned t = blockIdx.x * 256 + threadIdx.x;
    if (t < cnt) {
        int n = (int)g_hflag[t];
        unsigned long long key = g_res[n];
        g_idx[n] = (int)(0xFFFFFFFFu - (unsigned)(key & 0xFFFFFFFFull));
    }
}

// ---------------------------------------------------------------------------
// Gather: 8 rows per block
// ---------------------------------------------------------------------------
__global__ void gather_kernel(const float* __restrict__ W,
                              float* __restrict__ outq,
                              float* __restrict__ outi,
                              int write_idx) {
    int n = blockIdx.x * 8 + (threadIdx.x >> 5);
    int lane = threadIdx.x & 31;
    int idx = g_idx[n];
    const float4* src = (const float4*)(W + (size_t)idx * Dd);
    float4* dst = (float4*)(outq + (size_t)n * Dd);
    dst[lane] = src[lane];
    dst[lane + 32] = src[lane + 32];
    if (lane == 0 && write_idx) outi[n] = (float)idx;
}

// ---------------------------------------------------------------------------
extern "C" void kernel_launch(void* const* d_in, const int* in_sizes, int n_in,
                              void* d_out, int out_size) {
    const float* X = (const float*)d_in[0];
    const float* W = (const float*)d_in[1];
    float* out = (float*)d_out;

    cudaFuncSetAttribute(stage1_kernel,
                         cudaFuncAttributeMaxDynamicSharedMemorySize, SMEM_TOTAL);
    cudaFuncSetAttribute(heavy_kernel,
                         cudaFuncAttributeMaxDynamicSharedMemorySize, RS_SMEM);

    prep_kernel<<<CVX_BLKS + CVW_BLKS + WN_BLKS, 256>>>(X, W);

    stage1_kernel<<<(Nn / BM) * NSPLIT, 256, SMEM_TOTAL>>>();
    merge_kernel<<<Nn / 256, 256>>>();

    heavy_kernel<<<(CAPH / RROWS) * KSPLIT, 256, RS_SMEM>>>(X, W);
    apply_kernel<<<(CAPH + 255) / 256, 256>>>();

    int write_idx = (out_size >= Nn * Dd + Nn) ? 1 : 0;
    gather_kernel<<<Nn / 8, 256>>>(W, out, out + (size_t)Nn * Dd, write_idx);
}

// round 15
// speedup vs baseline: 1.1920x; 1.0651x over previous
#include <cuda_runtime.h>
#include <cuda_fp16.h>
#include <cstdint>

#define Nn 32768
#define Dd 256
#define Kk 8192

#define BM 128
#define BN 64
#define BK 32
#define NSPLIT 4
#define KSEG (Kk / NSPLIT)          // 2048 codewords per CTA
#define NCHUNK (KSEG / BN)          // 32 chunks
#define CAPH 8192u
#define MARGIN 0.05f
#define KSPLIT 8

// ---------------------------------------------------------------------------
// Device scratch
// ---------------------------------------------------------------------------
__device__ __half g_xh[Nn * Dd];
__device__ __half g_wh[Kk * Dd];
__device__ float g_wn[Kk];
__device__ int g_idx[Nn];
__device__ float g_pb1[Nn * NSPLIT];
__device__ float g_pb2[Nn * NSPLIT];
__device__ int   g_pidx[Nn * NSPLIT];
__device__ unsigned int g_hflag[CAPH];
__device__ unsigned int g_nh;
__device__ unsigned long long g_res[Nn];

// ---------------------------------------------------------------------------
__device__ __forceinline__ uint32_t smem_to_u32(const void* p) {
    uint32_t a;
    asm("{ .reg .u64 t; cvta.to.shared.u64 t, %1; cvt.u32.u64 %0, t; }"
        : "=r"(a) : "l"(p));
    return a;
}

__device__ __forceinline__ void cpasync16(uint32_t dst, const void* src) {
    asm volatile("cp.async.cg.shared.global [%0], [%1], 16;" :: "r"(dst), "l"(src));
}

#define CP_COMMIT() asm volatile("cp.async.commit_group;" ::: "memory")
#define CP_WAIT2()  asm volatile("cp.async.wait_group 2;" ::: "memory")

#define LDSM_X4(r0, r1, r2, r3, addr) \
    asm volatile("ldmatrix.sync.aligned.m8n8.x4.shared.b16 {%0,%1,%2,%3}, [%4];" \
        : "=r"(r0), "=r"(r1), "=r"(r2), "=r"(r3) : "r"(addr))

#define MMA16816(c, a, b) \
    asm volatile("mma.sync.aligned.m16n8k16.row.col.f32.f16.f16.f32 " \
        "{%0,%1,%2,%3}, {%4,%5,%6,%7}, {%8,%9}, {%0,%1,%2,%3};" \
        : "+f"((c)[0]), "+f"((c)[1]), "+f"((c)[2]), "+f"((c)[3]) \
        : "r"((a)[0]), "r"((a)[1]), "r"((a)[2]), "r"((a)[3]), \
          "r"((b)[0]), "r"((b)[1]))

__device__ __forceinline__ unsigned long long pack_key(float s, int k) {
    unsigned u = __float_as_uint(s);
    u = (u & 0x80000000u) ? ~u : (u | 0x80000000u);
    return ((unsigned long long)u << 32) | (unsigned long long)(0xFFFFFFFFu - (unsigned)k);
}

// SMEM layout (stage1, dynamic), 80B pitch:
//  4 stages x (A 128x80 + B 64x80) = 4 x 15360 = 61440
//  wns[2][64] = 512 ; merge mv1/mv2 (128x8 f32) + mi
#define SM_STAGE  15360
#define ATILE 0
#define BTILE 10240
#define SM_WNS    61440
#define SM_MV1    61952
#define SM_MV2    66048
#define SM_MI     70144
#define SMEM_TOTAL 74240

// ---------------------------------------------------------------------------
// Fused preprocessing: convx | convw | wnorm by block range
// ---------------------------------------------------------------------------
#define CVX_BLKS 16384
#define CVW_BLKS 4096
#define WN_BLKS  1024

__global__ void prep_kernel(const float* __restrict__ X, const float* __restrict__ W) {
    int b = blockIdx.x;
    if (b == 0 && threadIdx.x == 0) g_nh = 0;
    if (b < CVX_BLKS) {
        int i = b * 256 + threadIdx.x;
        float2 v = ((const float2*)X)[i];
        ((__half2*)g_xh)[i] = __halves2half2(__float2half(v.x), __float2half(v.y));
    } else if (b < CVX_BLKS + CVW_BLKS) {
        int i = (b - CVX_BLKS) * 256 + threadIdx.x;
        float2 v = ((const float2*)W)[i];
        ((__half2*)g_wh)[i] = __halves2half2(__float2half(v.x), __float2half(v.y));
    } else {
        int k = (b - CVX_BLKS - CVW_BLKS) * 8 + (threadIdx.x >> 5);
        int lane = threadIdx.x & 31;
        const float4* wp = (const float4*)(W + (size_t)k * Dd);
        float4 a = wp[lane * 2];
        float4 c = wp[lane * 2 + 1];
        float s = a.x * a.x + a.y * a.y + a.z * a.z + a.w * a.w
                + c.x * c.x + c.y * c.y + c.z * c.z + c.w * c.w;
        #pragma unroll
        for (int o = 16; o > 0; o >>= 1) s += __shfl_xor_sync(0xffffffffu, s, o);
        if (lane == 0) g_wn[k] = 0.5f * s;
    }
}

// ---------------------------------------------------------------------------
// Stage 1: fp16 warp-MMA GEMM, CTA = 128 rows x 2048 codewords (K-split 4),
// warp tile 32x32, 4-stage pipeline with incremental bookkeeping, 3 CTAs/SM.
// ---------------------------------------------------------------------------
__global__ void __launch_bounds__(256, 3) stage1_kernel() {
    extern __shared__ char smem[];
    const uint32_t sbase = smem_to_u32(smem);
    float* wnsS = (float*)(smem + SM_WNS);
    float* mv1 = (float*)(smem + SM_MV1);
    float* mv2 = (float*)(smem + SM_MV2);
    int*   mi  = (int*)(smem + SM_MI);

    const int tid = threadIdx.x;
    const int lane = tid & 31;
    const int wid = tid >> 5;
    const int warp_m = wid & 3;
    const int warp_n = wid >> 2;
    const int row0 = (blockIdx.x >> 2) * BM;
    const int split = blockIdx.x & 3;
    const int k0 = split * KSEG;

    const uint32_t laneA = (uint32_t)(ATILE +
        (warp_m * 32 + (lane & 15)) * 80 + (lane >> 4) * 16);
    const uint32_t laneB = (uint32_t)(BTILE +
        (warp_n * 32 + (lane & 7) + ((lane >> 4) & 1) * 8) * 80 +
        ((lane >> 3) & 1) * 16);

    const int aRow = tid >> 1;
    const int aC0 = (tid & 1) * 2;
    const int bRow = tid >> 2;
    const int bC = tid & 3;
    const uint32_t aDst = (uint32_t)(ATILE + aRow * 80 + aC0 * 16);
    const uint32_t bDst = (uint32_t)(BTILE + bRow * 80 + bC * 16);

    uint32_t s0 = sbase;
    uint32_t s1 = sbase + SM_STAGE;
    uint32_t s2 = sbase + 2 * SM_STAGE;
    uint32_t s3 = sbase + 3 * SM_STAGE;

    {
        const __half* aS = g_xh + (size_t)(row0 + aRow) * Dd + aC0 * 8;
        const __half* bS = g_wh + (size_t)(k0 + bRow) * Dd + bC * 8;
        uint32_t st[3] = { s0, s1, s2 };
        #pragma unroll
        for (int p = 0; p < 3; p++) {
            cpasync16(st[p] + aDst, aS + p * BK);
            cpasync16(st[p] + aDst + 16, aS + p * BK + 8);
            cpasync16(st[p] + bDst, bS + p * BK);
            CP_COMMIT();
        }
    }
    if (tid < BN) wnsS[tid] = g_wn[k0 + tid];

    const __half* aPref = g_xh + (size_t)(row0 + aRow) * Dd + aC0 * 8 + 3 * BK;
    const __half* bPref = g_wh + (size_t)(k0 + bRow) * Dd + bC * 8 + 3 * BK;
    int pkt = 3, pch = 0;

    float best1[4], best2[4];
    int idx1[4];
    #pragma unroll
    for (int r = 0; r < 4; r++) { best1[r] = -3.4e38f; best2[r] = -3.4e38f; idx1[r] = 0; }

    for (int ch = 0; ch < NCHUNK; ch++) {
        float acc[2][4][4];
        #pragma unroll
        for (int i = 0; i < 2; i++)
            #pragma unroll
            for (int j = 0; j < 4; j++)
                #pragma unroll
                for (int q = 0; q < 4; q++) acc[i][j][q] = 0.0f;

        #pragma unroll
        for (int kt = 0; kt < 8; kt++) {
            CP_WAIT2();
            __syncthreads();

            if (kt == 0 && ch + 1 < NCHUNK && tid < BN)
                wnsS[((ch + 1) & 1) * BN + tid] = g_wn[k0 + (ch + 1) * BN + tid];

            cpasync16(s3 + aDst, aPref);
            cpasync16(s3 + aDst + 16, aPref + 8);
            cpasync16(s3 + bDst, bPref);
            CP_COMMIT();
            if (++pkt == 8) {
                pkt = 0;
                aPref -= 7 * BK;
                bPref += BN * Dd - 7 * BK;
                if (++pch == NCHUNK) { pch = 0; bPref -= (size_t)KSEG * Dd; }
            } else {
                aPref += BK;
                bPref += BK;
            }

            #pragma unroll
            for (int ks = 0; ks < 2; ks++) {
                uint32_t a[2][4];
                #pragma unroll
                for (int i = 0; i < 2; i++)
                    LDSM_X4(a[i][0], a[i][1], a[i][2], a[i][3],
                            s0 + laneA + (uint32_t)(i * 1280 + ks * 32));
                uint32_t b[4][2];
                LDSM_X4(b[0][0], b[0][1], b[1][0], b[1][1],
                        s0 + laneB + (uint32_t)(ks * 32));
                LDSM_X4(b[2][0], b[2][1], b[3][0], b[3][1],
                        s0 + laneB + (uint32_t)(1280 + ks * 32));
                #pragma unroll
                for (int i = 0; i < 2; i++)
                    #pragma unroll
                    for (int j = 0; j < 4; j++)
                        MMA16816(acc[i][j], a[i], b[j]);
            }

            uint32_t t = s0; s0 = s1; s1 = s2; s2 = s3; s3 = t;
        }

        const int kc = k0 + ch * BN;
        const float* wn = wnsS + (ch & 1) * BN;
        #pragma unroll
        for (int i = 0; i < 2; i++) {
            #pragma unroll
            for (int h = 0; h < 2; h++) {
                const int r = i * 2 + h;
                #pragma unroll
                for (int j = 0; j < 4; j++) {
                    int col = warp_n * 32 + j * 8 + (lane & 3) * 2;
                    #pragma unroll
                    for (int q = 0; q < 2; q++) {
                        float s = acc[i][j][h * 2 + q] - wn[col + q];
                        int k = kc + col + q;
                        if (s > best1[r]) { best2[r] = best1[r]; best1[r] = s; idx1[r] = k; }
                        else if (s > best2[r]) { best2[r] = s; }
                    }
                }
            }
        }
    }

    const int e = warp_n * 4 + (lane & 3);
    #pragma unroll
    for (int r = 0; r < 4; r++) {
        int row = warp_m * 32 + (r >> 1) * 16 + (lane >> 2) + (r & 1) * 8;
        mv1[row * 8 + e] = best1[r];
        mv2[row * 8 + e] = best2[r];
        mi[row * 8 + e] = idx1[r];
    }
    __syncthreads();

    if (tid < BM) {
        float b1 = -3.4e38f, b2 = -3.4e38f;
        int bi = 0;
        #pragma unroll
        for (int t = 0; t < 8; t++) {
            float v = mv1[tid * 8 + t];
            int ii = mi[tid * 8 + t];
            if (v > b1 || (v == b1 && ii < bi)) { b2 = (b2 > b1) ? b2 : b1; b1 = v; bi = ii; }
            else if (v > b2) b2 = v;
            float v2 = mv2[tid * 8 + t];
            if (v2 > b2) b2 = v2;
        }
        int n = row0 + tid;
        g_pb1[n * NSPLIT + split] = b1;
        g_pb2[n * NSPLIT + split] = b2;
        g_pidx[n * NSPLIT + split] = bi;
    }
}

// ---------------------------------------------------------------------------
// Merge partials across 4 K-splits; write g_idx; flag margin rows
// ---------------------------------------------------------------------------
__global__ void merge_kernel() {
    int n = blockIdx.x * 256 + threadIdx.x;
    float b1 = -3.4e38f, b2 = -3.4e38f;
    int bi = 0;
    #pragma unroll
    for (int s = 0; s < NSPLIT; s++) {
        float v = g_pb1[n * NSPLIT + s];
        int ii = g_pidx[n * NSPLIT + s];
        float v2 = g_pb2[n * NSPLIT + s];
        if (v > b1 || (v == b1 && ii < bi)) { b2 = (b2 > b1) ? b2 : b1; b1 = v; bi = ii; }
        else if (v > b2) b2 = v;
        if (v2 > b2) b2 = v2;
    }
    g_idx[n] = bi;
    if (b1 - b2 < MARGIN) {
        unsigned slot = atomicAdd(&g_nh, 1u);
        if (slot < CAPH) {
            g_res[n] = 0ull;
            __threadfence();
            g_hflag[slot] = n;
        }
    }
}

// ---------------------------------------------------------------------------
// Heavy rescue: 32 rows/block x 1024-codeword K-split, 4 rows/thread.
// 66 KB smem -> 3 CTAs/SM. Exact fp32; atomicMax combine.
// ---------------------------------------------------------------------------
#define WPITCH 260
#define RROWS 32
#define RS_XS 0
#define RS_WS (RROWS * 256 * 4)                 // 32768
#define RS_SMEM (RS_WS + 32 * WPITCH * 4)       // 66048 bytes

__global__ void __launch_bounds__(256) heavy_kernel(const float* __restrict__ X,
                                                    const float* __restrict__ W) {
    extern __shared__ char rsm[];
    float* xs = (float*)(rsm + RS_XS);          // [32][256]
    float* ws = (float*)(rsm + RS_WS);          // [32 * WPITCH]

    unsigned cnt = g_nh; if (cnt > CAPH) cnt = CAPH;
    const unsigned grp = blockIdx.x >> 3;          // row group (32 rows)
    const int ksp = blockIdx.x & 7;
    if (grp * RROWS >= cnt) return;

    const int tid = threadIdx.x;
    const int w = tid >> 5;                        // warp: owns rows w*4..w*4+3
    const int tx = tid & 31;

    // load 32 X rows: 2048 float4, 8 per thread
    #pragma unroll
    for (int q = 0; q < 8; q++) {
        int f = q * 256 + tid;
        int r = f >> 6, seg = f & 63;
        unsigned slot = grp * RROWS + r;
        int n = (int)g_hflag[slot < cnt ? slot : (grp * RROWS)];
        *(float4*)&xs[r * 256 + seg * 4] =
            ((const float4*)(X + (size_t)n * Dd))[seg];
    }

    unsigned long long key[4];
    #pragma unroll
    for (int i = 0; i < 4; i++) key[i] = 0ull;

    const int k0 = ksp * (Kk / KSPLIT);
    for (int kc = 0; kc < Kk / KSPLIT; kc += 32) {
        __syncthreads();
        // stage 32 codewords
        {
            const int kr = tid >> 3, seg = tid & 7;
            const float4* src = (const float4*)(W + (size_t)(k0 + kc + kr) * Dd);
            #pragma unroll
            for (int q = 0; q < 8; q++)
                *(float4*)&ws[kr * WPITCH + (seg * 8 + q) * 4] = src[seg * 8 + q];
        }
        __syncthreads();

        const int k = k0 + kc + tx;
        float dot[4];
        #pragma unroll
        for (int i = 0; i < 4; i++) dot[i] = 0.0f;
        #pragma unroll
        for (int d = 0; d < 256; d += 4) {
            float4 wv = *(const float4*)&ws[tx * WPITCH + d];
            #pragma unroll
            for (int i = 0; i < 4; i++) {
                float4 xv = *(const float4*)&xs[(w * 4 + i) * 256 + d];
                dot[i] += wv.x * xv.x + wv.y * xv.y + wv.z * xv.z + wv.w * xv.w;
            }
        }
        const float wn = g_wn[k];
        #pragma unroll
        for (int i = 0; i < 4; i++) {
            unsigned long long kk2 = pack_key(dot[i] - wn, k);
            if (kk2 > key[i]) key[i] = kk2;
        }
    }

    #pragma unroll
    for (int i = 0; i < 4; i++) {
        unsigned long long kv = key[i];
        #pragma unroll
        for (int o = 16; o > 0; o >>= 1) {
            unsigned long long other = __shfl_xor_sync(0xffffffffu, kv, o);
            if (other > kv) kv = other;
        }
        if (tx == 0) {
            unsigned slot = grp * RROWS + w * 4 + i;
            if (slot < cnt) atomicMax(&g_res[g_hflag[slot]], kv);
        }
    }
}

__global__ void apply_kernel() {
    unsigned cnt = g_nh; if (cnt > CAPH) cnt = CAPH;
    unsigned t = blockIdx.x * 256 + threadIdx.x;
    if (t < cnt) {
        int n = (int)g_hflag[t];
        unsigned long long key = g_res[n];
        g_idx[n] = (int)(0xFFFFFFFFu - (unsigned)(key & 0xFFFFFFFFull));
    }
}

// ---------------------------------------------------------------------------
// Gather: 8 rows per block
// ---------------------------------------------------------------------------
__global__ void gather_kernel(const float* __restrict__ W,
                              float* __restrict__ outq,
                              float* __restrict__ outi,
                              int write_idx) {
    int n = blockIdx.x * 8 + (threadIdx.x >> 5);
    int lane = threadIdx.x & 31;
    int idx = g_idx[n];
    const float4* src = (const float4*)(W + (size_t)idx * Dd);
    float4* dst = (float4*)(outq + (size_t)n * Dd);
    dst[lane] = src[lane];
    dst[lane + 32] = src[lane + 32];
    if (lane == 0 && write_idx) outi[n] = (float)idx;
}

// ---------------------------------------------------------------------------
extern "C" void kernel_launch(void* const* d_in, const int* in_sizes, int n_in,
                              void* d_out, int out_size) {
    const float* X = (const float*)d_in[0];
    const float* W = (const float*)d_in[1];
    float* out = (float*)d_out;

    cudaFuncSetAttribute(stage1_kernel,
                         cudaFuncAttributeMaxDynamicSharedMemorySize, SMEM_TOTAL);
    cudaFuncSetAttribute(heavy_kernel,
                         cudaFuncAttributeMaxDynamicSharedMemorySize, RS_SMEM);

    prep_kernel<<<CVX_BLKS + CVW_BLKS + WN_BLKS, 256>>>(X, W);

    stage1_kernel<<<(Nn / BM) * NSPLIT, 256, SMEM_TOTAL>>>();
    merge_kernel<<<Nn / 256, 256>>>();

    heavy_kernel<<<(CAPH / RROWS) * KSPLIT, 256, RS_SMEM>>>(X, W);
    apply_kernel<<<(CAPH + 255) / 256, 256>>>();

    int write_idx = (out_size >= Nn * Dd + Nn) ? 1 : 0;
    gather_kernel<<<Nn / 8, 256>>>(W, out, out + (size_t)Nn * Dd, write_idx);
}

// round 16
// speedup vs baseline: 1.4427x; 1.2103x over previous
#include <cuda_runtime.h>
#include <cuda_fp16.h>
#include <cstdint>

#define Nn 32768
#define Dd 256
#define Kk 8192

#define BM 128
#define BN 64
#define BK 32
#define NSPLIT 4
#define KSEG (Kk / NSPLIT)          // 2048 codewords per CTA
#define NCHUNK (KSEG / BN)          // 32 chunks
#define CAPF 8192u
#define CAP_S 4096u
#define MARGIN 0.05f

// ---------------------------------------------------------------------------
// Device scratch
// ---------------------------------------------------------------------------
__device__ __half g_xh[Nn * Dd];
__device__ __half g_wh[Kk * Dd];
__device__ float g_wn[Kk];
__device__ int g_idx[Nn];
__device__ float g_pb1[Nn * NSPLIT];
__device__ float g_pb2[Nn * NSPLIT];
__device__ int   g_pidx[Nn * NSPLIT];
__device__ unsigned int g_flag[CAPF];
__device__ unsigned int g_nf;
__device__ unsigned int g_hlist[NSPLIT * CAP_S];
__device__ unsigned int g_nhs[NSPLIT];
__device__ unsigned long long g_res[Nn];

// ---------------------------------------------------------------------------
__device__ __forceinline__ uint32_t smem_to_u32(const void* p) {
    uint32_t a;
    asm("{ .reg .u64 t; cvta.to.shared.u64 t, %1; cvt.u32.u64 %0, t; }"
        : "=r"(a) : "l"(p));
    return a;
}

__device__ __forceinline__ void cpasync16(uint32_t dst, const void* src) {
    asm volatile("cp.async.cg.shared.global [%0], [%1], 16;" :: "r"(dst), "l"(src));
}

#define CP_COMMIT() asm volatile("cp.async.commit_group;" ::: "memory")
#define CP_WAIT2()  asm volatile("cp.async.wait_group 2;" ::: "memory")

#define LDSM_X4(r0, r1, r2, r3, addr) \
    asm volatile("ldmatrix.sync.aligned.m8n8.x4.shared.b16 {%0,%1,%2,%3}, [%4];" \
        : "=r"(r0), "=r"(r1), "=r"(r2), "=r"(r3) : "r"(addr))

#define MMA16816(c, a, b) \
    asm volatile("mma.sync.aligned.m16n8k16.row.col.f32.f16.f16.f32 " \
        "{%0,%1,%2,%3}, {%4,%5,%6,%7}, {%8,%9}, {%0,%1,%2,%3};" \
        : "+f"((c)[0]), "+f"((c)[1]), "+f"((c)[2]), "+f"((c)[3]) \
        : "r"((a)[0]), "r"((a)[1]), "r"((a)[2]), "r"((a)[3]), \
          "r"((b)[0]), "r"((b)[1]))

__device__ __forceinline__ unsigned long long pack_key(float s, int k) {
    unsigned u = __float_as_uint(s);
    u = (u & 0x80000000u) ? ~u : (u | 0x80000000u);
    return ((unsigned long long)u << 32) | (unsigned long long)(0xFFFFFFFFu - (unsigned)k);
}

// SMEM layout (stage1, dynamic), 80B pitch:
#define SM_STAGE  15360
#define ATILE 0
#define BTILE 10240
#define SM_WNS    61440
#define SM_MV1    61952
#define SM_MV2    66048
#define SM_MI     70144
#define SMEM_TOTAL 74240

// ---------------------------------------------------------------------------
// Fused preprocessing: convx | convw | wnorm by block range
// ---------------------------------------------------------------------------
#define CVX_BLKS 16384
#define CVW_BLKS 4096
#define WN_BLKS  1024

__global__ void prep_kernel(const float* __restrict__ X, const float* __restrict__ W) {
    int b = blockIdx.x;
    if (b == 0 && threadIdx.x < 8) {
        if (threadIdx.x == 0) g_nf = 0;
        if (threadIdx.x < NSPLIT) g_nhs[threadIdx.x] = 0;
    }
    if (b < CVX_BLKS) {
        int i = b * 256 + threadIdx.x;
        float2 v = ((const float2*)X)[i];
        ((__half2*)g_xh)[i] = __halves2half2(__float2half(v.x), __float2half(v.y));
    } else if (b < CVX_BLKS + CVW_BLKS) {
        int i = (b - CVX_BLKS) * 256 + threadIdx.x;
        float2 v = ((const float2*)W)[i];
        ((__half2*)g_wh)[i] = __halves2half2(__float2half(v.x), __float2half(v.y));
    } else {
        int k = (b - CVX_BLKS - CVW_BLKS) * 8 + (threadIdx.x >> 5);
        int lane = threadIdx.x & 31;
        const float4* wp = (const float4*)(W + (size_t)k * Dd);
        float4 a = wp[lane * 2];
        float4 c = wp[lane * 2 + 1];
        float s = a.x * a.x + a.y * a.y + a.z * a.z + a.w * a.w
                + c.x * c.x + c.y * c.y + c.z * c.z + c.w * c.w;
        #pragma unroll
        for (int o = 16; o > 0; o >>= 1) s += __shfl_xor_sync(0xffffffffu, s, o);
        if (lane == 0) g_wn[k] = 0.5f * s;
    }
}

// ---------------------------------------------------------------------------
// Stage 1: fp16 warp-MMA GEMM (unchanged from round 15)
// ---------------------------------------------------------------------------
__global__ void __launch_bounds__(256, 3) stage1_kernel() {
    extern __shared__ char smem[];
    const uint32_t sbase = smem_to_u32(smem);
    float* wnsS = (float*)(smem + SM_WNS);
    float* mv1 = (float*)(smem + SM_MV1);
    float* mv2 = (float*)(smem + SM_MV2);
    int*   mi  = (int*)(smem + SM_MI);

    const int tid = threadIdx.x;
    const int lane = tid & 31;
    const int wid = tid >> 5;
    const int warp_m = wid & 3;
    const int warp_n = wid >> 2;
    const int row0 = (blockIdx.x >> 2) * BM;
    const int split = blockIdx.x & 3;
    const int k0 = split * KSEG;

    const uint32_t laneA = (uint32_t)(ATILE +
        (warp_m * 32 + (lane & 15)) * 80 + (lane >> 4) * 16);
    const uint32_t laneB = (uint32_t)(BTILE +
        (warp_n * 32 + (lane & 7) + ((lane >> 4) & 1) * 8) * 80 +
        ((lane >> 3) & 1) * 16);

    const int aRow = tid >> 1;
    const int aC0 = (tid & 1) * 2;
    const int bRow = tid >> 2;
    const int bC = tid & 3;
    const uint32_t aDst = (uint32_t)(ATILE + aRow * 80 + aC0 * 16);
    const uint32_t bDst = (uint32_t)(BTILE + bRow * 80 + bC * 16);

    uint32_t s0 = sbase;
    uint32_t s1 = sbase + SM_STAGE;
    uint32_t s2 = sbase + 2 * SM_STAGE;
    uint32_t s3 = sbase + 3 * SM_STAGE;

    {
        const __half* aS = g_xh + (size_t)(row0 + aRow) * Dd + aC0 * 8;
        const __half* bS = g_wh + (size_t)(k0 + bRow) * Dd + bC * 8;
        uint32_t st[3] = { s0, s1, s2 };
        #pragma unroll
        for (int p = 0; p < 3; p++) {
            cpasync16(st[p] + aDst, aS + p * BK);
            cpasync16(st[p] + aDst + 16, aS + p * BK + 8);
            cpasync16(st[p] + bDst, bS + p * BK);
            CP_COMMIT();
        }
    }
    if (tid < BN) wnsS[tid] = g_wn[k0 + tid];

    const __half* aPref = g_xh + (size_t)(row0 + aRow) * Dd + aC0 * 8 + 3 * BK;
    const __half* bPref = g_wh + (size_t)(k0 + bRow) * Dd + bC * 8 + 3 * BK;
    int pkt = 3, pch = 0;

    float best1[4], best2[4];
    int idx1[4];
    #pragma unroll
    for (int r = 0; r < 4; r++) { best1[r] = -3.4e38f; best2[r] = -3.4e38f; idx1[r] = 0; }

    for (int ch = 0; ch < NCHUNK; ch++) {
        float acc[2][4][4];
        #pragma unroll
        for (int i = 0; i < 2; i++)
            #pragma unroll
            for (int j = 0; j < 4; j++)
                #pragma unroll
                for (int q = 0; q < 4; q++) acc[i][j][q] = 0.0f;

        #pragma unroll
        for (int kt = 0; kt < 8; kt++) {
            CP_WAIT2();
            __syncthreads();

            if (kt == 0 && ch + 1 < NCHUNK && tid < BN)
                wnsS[((ch + 1) & 1) * BN + tid] = g_wn[k0 + (ch + 1) * BN + tid];

            cpasync16(s3 + aDst, aPref);
            cpasync16(s3 + aDst + 16, aPref + 8);
            cpasync16(s3 + bDst, bPref);
            CP_COMMIT();
            if (++pkt == 8) {
                pkt = 0;
                aPref -= 7 * BK;
                bPref += BN * Dd - 7 * BK;
                if (++pch == NCHUNK) { pch = 0; bPref -= (size_t)KSEG * Dd; }
            } else {
                aPref += BK;
                bPref += BK;
            }

            #pragma unroll
            for (int ks = 0; ks < 2; ks++) {
                uint32_t a[2][4];
                #pragma unroll
                for (int i = 0; i < 2; i++)
                    LDSM_X4(a[i][0], a[i][1], a[i][2], a[i][3],
                            s0 + laneA + (uint32_t)(i * 1280 + ks * 32));
                uint32_t b[4][2];
                LDSM_X4(b[0][0], b[0][1], b[1][0], b[1][1],
                        s0 + laneB + (uint32_t)(ks * 32));
                LDSM_X4(b[2][0], b[2][1], b[3][0], b[3][1],
                        s0 + laneB + (uint32_t)(1280 + ks * 32));
                #pragma unroll
                for (int i = 0; i < 2; i++)
                    #pragma unroll
                    for (int j = 0; j < 4; j++)
                        MMA16816(acc[i][j], a[i], b[j]);
            }

            uint32_t t = s0; s0 = s1; s1 = s2; s2 = s3; s3 = t;
        }

        const int kc = k0 + ch * BN;
        const float* wn = wnsS + (ch & 1) * BN;
        #pragma unroll
        for (int i = 0; i < 2; i++) {
            #pragma unroll
            for (int h = 0; h < 2; h++) {
                const int r = i * 2 + h;
                #pragma unroll
                for (int j = 0; j < 4; j++) {
                    int col = warp_n * 32 + j * 8 + (lane & 3) * 2;
                    #pragma unroll
                    for (int q = 0; q < 2; q++) {
                        float s = acc[i][j][h * 2 + q] - wn[col + q];
                        int k = kc + col + q;
                        if (s > best1[r]) { best2[r] = best1[r]; best1[r] = s; idx1[r] = k; }
                        else if (s > best2[r]) { best2[r] = s; }
                    }
                }
            }
        }
    }

    const int e = warp_n * 4 + (lane & 3);
    #pragma unroll
    for (int r = 0; r < 4; r++) {
        int row = warp_m * 32 + (r >> 1) * 16 + (lane >> 2) + (r & 1) * 8;
        mv1[row * 8 + e] = best1[r];
        mv2[row * 8 + e] = best2[r];
        mi[row * 8 + e] = idx1[r];
    }
    __syncthreads();

    if (tid < BM) {
        float b1 = -3.4e38f, b2 = -3.4e38f;
        int bi = 0;
        #pragma unroll
        for (int t = 0; t < 8; t++) {
            float v = mv1[tid * 8 + t];
            int ii = mi[tid * 8 + t];
            if (v > b1 || (v == b1 && ii < bi)) { b2 = (b2 > b1) ? b2 : b1; b1 = v; bi = ii; }
            else if (v > b2) b2 = v;
            float v2 = mv2[tid * 8 + t];
            if (v2 > b2) b2 = v2;
        }
        int n = row0 + tid;
        g_pb1[n * NSPLIT + split] = b1;
        g_pb2[n * NSPLIT + split] = b2;
        g_pidx[n * NSPLIT + split] = bi;
    }
}

// ---------------------------------------------------------------------------
// Merge: combine splits, flag rows, and build per-split heavy lists.
//   candidate rule: split can contribute in-window k beyond its pidx only
//   if its (exact, per-split) second-best >= thr.
// ---------------------------------------------------------------------------
__global__ void merge_kernel() {
    int n = blockIdx.x * 256 + threadIdx.x;
    float b1 = -3.4e38f, b2 = -3.4e38f;
    int bi = 0;
    #pragma unroll
    for (int s = 0; s < NSPLIT; s++) {
        float v = g_pb1[n * NSPLIT + s];
        int ii = g_pidx[n * NSPLIT + s];
        float v2 = g_pb2[n * NSPLIT + s];
        if (v > b1 || (v == b1 && ii < bi)) { b2 = (b2 > b1) ? b2 : b1; b1 = v; bi = ii; }
        else if (v > b2) b2 = v;
        if (v2 > b2) b2 = v2;
    }
    g_idx[n] = bi;

    const float thr = b1 - MARGIN;
    int nc = 0, hmask = 0;
    #pragma unroll
    for (int s = 0; s < NSPLIT; s++) {
        if (g_pb1[n * NSPLIT + s] >= thr) nc++;
        if (g_pb2[n * NSPLIT + s] >= thr) hmask |= (1 << s);
    }

    if (nc >= 2 || hmask) {
        g_res[n] = 0ull;
        unsigned slot = atomicAdd(&g_nf, 1u);
        if (slot < CAPF) g_flag[slot] = n;
        #pragma unroll
        for (int s = 0; s < NSPLIT; s++) {
            if (hmask & (1 << s)) {
                unsigned h = atomicAdd(&g_nhs[s], 1u);
                if (h < CAP_S) g_hlist[s * CAP_S + h] = n;
            }
        }
    }
}

// ---------------------------------------------------------------------------
// Candidate rescore: one warp per flagged row; exact fp32 of the 4 split-pidx.
// ---------------------------------------------------------------------------
__global__ void __launch_bounds__(256) cand_kernel(const float* __restrict__ X,
                                                   const float* __restrict__ W) {
    unsigned cnt = g_nf; if (cnt > CAPF) cnt = CAPF;
    unsigned r = blockIdx.x * 8 + (threadIdx.x >> 5);
    if (r >= cnt) return;
    const int lane = threadIdx.x & 31;
    const int n = (int)g_flag[r];

    const float4* xp = (const float4*)(X + (size_t)n * Dd);
    float4 x0 = xp[lane * 2];
    float4 x1 = xp[lane * 2 + 1];

    unsigned long long best = 0ull;
    #pragma unroll
    for (int s = 0; s < NSPLIT; s++) {
        int k = g_pidx[n * NSPLIT + s];
        const float4* wp = (const float4*)(W + (size_t)k * Dd);
        float4 w0 = wp[lane * 2];
        float4 w1 = wp[lane * 2 + 1];
        float dot = x0.x * w0.x + x0.y * w0.y + x0.z * w0.z + x0.w * w0.w
                  + x1.x * w1.x + x1.y * w1.y + x1.z * w1.z + x1.w * w1.w;
        #pragma unroll
        for (int o = 16; o > 0; o >>= 1) dot += __shfl_xor_sync(0xffffffffu, dot, o);
        unsigned long long key = pack_key(dot - g_wn[k], k);
        if (key > best) best = key;
    }
    if (lane == 0) atomicMax(&g_res[n], best);
}

// ---------------------------------------------------------------------------
// Heavy rescue: per (split, rowgroup of 32, 256-k subsegment).
// Only rows whose hmask includes this split. 4 rows/thread, exact fp32.
// ---------------------------------------------------------------------------
#define WPITCH 260
#define RROWS 32
#define RS_XS 0
#define RS_WS (RROWS * 256 * 4)                 // 32768
#define RS_SMEM (RS_WS + 32 * WPITCH * 4)       // 66048 bytes

__global__ void __launch_bounds__(256) heavy_kernel(const float* __restrict__ X,
                                                    const float* __restrict__ W) {
    extern __shared__ char rsm[];
    float* xs = (float*)(rsm + RS_XS);
    float* ws = (float*)(rsm + RS_WS);

    const int bx = blockIdx.x;
    const int s = bx & 3;                          // split
    const int sub = (bx >> 2) & 7;                 // 256-k subsegment
    const unsigned grp = (unsigned)(bx >> 5);      // row group

    unsigned cnt = g_nhs[s]; if (cnt > CAP_S) cnt = CAP_S;
    if (grp * RROWS >= cnt) return;

    const int tid = threadIdx.x;
    const int w = tid >> 5;
    const int tx = tid & 31;
    const unsigned* list = g_hlist + s * CAP_S;

    #pragma unroll
    for (int q = 0; q < 8; q++) {
        int f = q * 256 + tid;
        int r = f >> 6, seg = f & 63;
        unsigned slot = grp * RROWS + r;
        int n = (int)list[slot < cnt ? slot : (grp * RROWS)];
        *(float4*)&xs[r * 256 + seg * 4] =
            ((const float4*)(X + (size_t)n * Dd))[seg];
    }

    unsigned long long key[4];
    #pragma unroll
    for (int i = 0; i < 4; i++) key[i] = 0ull;

    const int k0 = s * KSEG + sub * 256;
    for (int kc = 0; kc < 256; kc += 32) {
        __syncthreads();
        {
            const int kr = tid >> 3, seg = tid & 7;
            const float4* src = (const float4*)(W + (size_t)(k0 + kc + kr) * Dd);
            #pragma unroll
            for (int q = 0; q < 8; q++)
                *(float4*)&ws[kr * WPITCH + (seg * 8 + q) * 4] = src[seg * 8 + q];
        }
        __syncthreads();

        const int k = k0 + kc + tx;
        float dot[4];
        #pragma unroll
        for (int i = 0; i < 4; i++) dot[i] = 0.0f;
        #pragma unroll
        for (int d = 0; d < 256; d += 4) {
            float4 wv = *(const float4*)&ws[tx * WPITCH + d];
            #pragma unroll
            for (int i = 0; i < 4; i++) {
                float4 xv = *(const float4*)&xs[(w * 4 + i) * 256 + d];
                dot[i] += wv.x * xv.x + wv.y * xv.y + wv.z * xv.z + wv.w * xv.w;
            }
        }
        const float wn = g_wn[k];
        #pragma unroll
        for (int i = 0; i < 4; i++) {
            unsigned long long kk2 = pack_key(dot[i] - wn, k);
            if (kk2 > key[i]) key[i] = kk2;
        }
    }

    #pragma unroll
    for (int i = 0; i < 4; i++) {
        unsigned long long kv = key[i];
        #pragma unroll
        for (int o = 16; o > 0; o >>= 1) {
            unsigned long long other = __shfl_xor_sync(0xffffffffu, kv, o);
            if (other > kv) kv = other;
        }
        if (tx == 0) {
            unsigned slot = grp * RROWS + w * 4 + i;
            if (slot < cnt) atomicMax(&g_res[list[slot]], kv);
        }
    }
}

__global__ void apply_kernel() {
    unsigned cnt = g_nf; if (cnt > CAPF) cnt = CAPF;
    unsigned t = blockIdx.x * 256 + threadIdx.x;
    if (t < cnt) {
        int n = (int)g_flag[t];
        unsigned long long key = g_res[n];
        g_idx[n] = (int)(0xFFFFFFFFu - (unsigned)(key & 0xFFFFFFFFull));
    }
}

// ---------------------------------------------------------------------------
// Gather: 8 rows per block
// ---------------------------------------------------------------------------
__global__ void gather_kernel(const float* __restrict__ W,
                              float* __restrict__ outq,
                              float* __restrict__ outi,
                              int write_idx) {
    int n = blockIdx.x * 8 + (threadIdx.x >> 5);
    int lane = threadIdx.x & 31;
    int idx = g_idx[n];
    const float4* src = (const float4*)(W + (size_t)idx * Dd);
    float4* dst = (float4*)(outq + (size_t)n * Dd);
    dst[lane] = src[lane];
    dst[lane + 32] = src[lane + 32];
    if (lane == 0 && write_idx) outi[n] = (float)idx;
}

// ---------------------------------------------------------------------------
extern "C" void kernel_launch(void* const* d_in, const int* in_sizes, int n_in,
                              void* d_out, int out_size) {
    const float* X = (const float*)d_in[0];
    const float* W = (const float*)d_in[1];
    float* out = (float*)d_out;

    cudaFuncSetAttribute(stage1_kernel,
                         cudaFuncAttributeMaxDynamicSharedMemorySize, SMEM_TOTAL);
    cudaFuncSetAttribute(heavy_kernel,
                         cudaFuncAttributeMaxDynamicSharedMemorySize, RS_SMEM);

    prep_kernel<<<CVX_BLKS + CVW_BLKS + WN_BLKS, 256>>>(X, W);

    stage1_kernel<<<(Nn / BM) * NSPLIT, 256, SMEM_TOTAL>>>();
    merge_kernel<<<Nn / 256, 256>>>();

    cand_kernel<<<CAPF / 8, 256>>>(X, W);
    heavy_kernel<<<NSPLIT * 8 * (CAP_S / RROWS), 256, RS_SMEM>>>(X, W);
    apply_kernel<<<(CAPF + 255) / 256, 256>>>();

    int write_idx = (out_size >= Nn * Dd + Nn) ? 1 : 0;
    gather_kernel<<<Nn / 8, 256>>>(W, out, out + (size_t)Nn * Dd, write_idx);
}

// round 17
// speedup vs baseline: 1.4539x; 1.0078x over previous
#include <cuda_runtime.h>
#include <cuda_fp16.h>
#include <cstdint>

#define Nn 32768
#define Dd 256
#define Kk 8192

#define BM 128
#define BN 64
#define BK 32
#define NSPLIT 8
#define KSEG (Kk / NSPLIT)          // 1024 codewords per CTA
#define NCHUNK (KSEG / BN)          // 16 chunks
#define CAPF 8192u
#define CAP_S 4096u
#define MARGIN 0.05f

// ---------------------------------------------------------------------------
// Device scratch
// ---------------------------------------------------------------------------
__device__ __half g_xh[Nn * Dd];
__device__ __half g_wh[Kk * Dd];
__device__ float g_wn[Kk];
__device__ int g_idx[Nn];
__device__ float g_pb1[Nn * NSPLIT];
__device__ float g_pb2[Nn * NSPLIT];
__device__ int   g_pidx[Nn * NSPLIT];
__device__ unsigned int g_flag[CAPF];
__device__ unsigned int g_nf;
__device__ unsigned int g_hlist[NSPLIT * CAP_S];
__device__ unsigned int g_nhs[NSPLIT];
__device__ unsigned long long g_res[Nn];

// ---------------------------------------------------------------------------
__device__ __forceinline__ uint32_t smem_to_u32(const void* p) {
    uint32_t a;
    asm("{ .reg .u64 t; cvta.to.shared.u64 t, %1; cvt.u32.u64 %0, t; }"
        : "=r"(a) : "l"(p));
    return a;
}

__device__ __forceinline__ void cpasync16(uint32_t dst, const void* src) {
    asm volatile("cp.async.cg.shared.global [%0], [%1], 16;" :: "r"(dst), "l"(src));
}

#define CP_COMMIT() asm volatile("cp.async.commit_group;" ::: "memory")
#define CP_WAIT2()  asm volatile("cp.async.wait_group 2;" ::: "memory")

#define LDSM_X4(r0, r1, r2, r3, addr) \
    asm volatile("ldmatrix.sync.aligned.m8n8.x4.shared.b16 {%0,%1,%2,%3}, [%4];" \
        : "=r"(r0), "=r"(r1), "=r"(r2), "=r"(r3) : "r"(addr))

#define MMA16816(c, a, b) \
    asm volatile("mma.sync.aligned.m16n8k16.row.col.f32.f16.f16.f32 " \
        "{%0,%1,%2,%3}, {%4,%5,%6,%7}, {%8,%9}, {%0,%1,%2,%3};" \
        : "+f"((c)[0]), "+f"((c)[1]), "+f"((c)[2]), "+f"((c)[3]) \
        : "r"((a)[0]), "r"((a)[1]), "r"((a)[2]), "r"((a)[3]), \
          "r"((b)[0]), "r"((b)[1]))

__device__ __forceinline__ unsigned long long pack_key(float s, int k) {
    unsigned u = __float_as_uint(s);
    u = (u & 0x80000000u) ? ~u : (u | 0x80000000u);
    return ((unsigned long long)u << 32) | (unsigned long long)(0xFFFFFFFFu - (unsigned)k);
}

// SMEM layout (stage1, dynamic), 80B pitch:
#define SM_STAGE  15360
#define ATILE 0
#define BTILE 10240
#define SM_WNS    61440
#define SM_MV1    61952
#define SM_MV2    66048
#define SM_MI     70144
#define SMEM_TOTAL 74240

// ---------------------------------------------------------------------------
// Fused preprocessing: convx | convw | wnorm by block range
// ---------------------------------------------------------------------------
#define CVX_BLKS 16384
#define CVW_BLKS 4096
#define WN_BLKS  1024

__global__ void prep_kernel(const float* __restrict__ X, const float* __restrict__ W) {
    int b = blockIdx.x;
    if (b == 0 && threadIdx.x < 16) {
        if (threadIdx.x == 0) g_nf = 0;
        if (threadIdx.x < NSPLIT) g_nhs[threadIdx.x] = 0;
    }
    if (b < CVX_BLKS) {
        int i = b * 256 + threadIdx.x;
        float2 v = ((const float2*)X)[i];
        ((__half2*)g_xh)[i] = __halves2half2(__float2half(v.x), __float2half(v.y));
    } else if (b < CVX_BLKS + CVW_BLKS) {
        int i = (b - CVX_BLKS) * 256 + threadIdx.x;
        float2 v = ((const float2*)W)[i];
        ((__half2*)g_wh)[i] = __halves2half2(__float2half(v.x), __float2half(v.y));
    } else {
        int k = (b - CVX_BLKS - CVW_BLKS) * 8 + (threadIdx.x >> 5);
        int lane = threadIdx.x & 31;
        const float4* wp = (const float4*)(W + (size_t)k * Dd);
        float4 a = wp[lane * 2];
        float4 c = wp[lane * 2 + 1];
        float s = a.x * a.x + a.y * a.y + a.z * a.z + a.w * a.w
                + c.x * c.x + c.y * c.y + c.z * c.z + c.w * c.w;
        #pragma unroll
        for (int o = 16; o > 0; o >>= 1) s += __shfl_xor_sync(0xffffffffu, s, o);
        if (lane == 0) g_wn[k] = 0.5f * s;
    }
}

// ---------------------------------------------------------------------------
// Stage 1: fp16 warp-MMA GEMM, CTA = 128 rows x 1024 codewords (K-split 8),
// warp tile 32x32, 4-stage pipeline with incremental bookkeeping, 3 CTAs/SM.
// ---------------------------------------------------------------------------
__global__ void __launch_bounds__(256, 3) stage1_kernel() {
    extern __shared__ char smem[];
    const uint32_t sbase = smem_to_u32(smem);
    float* wnsS = (float*)(smem + SM_WNS);
    float* mv1 = (float*)(smem + SM_MV1);
    float* mv2 = (float*)(smem + SM_MV2);
    int*   mi  = (int*)(smem + SM_MI);

    const int tid = threadIdx.x;
    const int lane = tid & 31;
    const int wid = tid >> 5;
    const int warp_m = wid & 3;
    const int warp_n = wid >> 2;
    const int row0 = (blockIdx.x >> 3) * BM;
    const int split = blockIdx.x & 7;
    const int k0 = split * KSEG;

    const uint32_t laneA = (uint32_t)(ATILE +
        (warp_m * 32 + (lane & 15)) * 80 + (lane >> 4) * 16);
    const uint32_t laneB = (uint32_t)(BTILE +
        (warp_n * 32 + (lane & 7) + ((lane >> 4) & 1) * 8) * 80 +
        ((lane >> 3) & 1) * 16);

    const int aRow = tid >> 1;
    const int aC0 = (tid & 1) * 2;
    const int bRow = tid >> 2;
    const int bC = tid & 3;
    const uint32_t aDst = (uint32_t)(ATILE + aRow * 80 + aC0 * 16);
    const uint32_t bDst = (uint32_t)(BTILE + bRow * 80 + bC * 16);

    uint32_t s0 = sbase;
    uint32_t s1 = sbase + SM_STAGE;
    uint32_t s2 = sbase + 2 * SM_STAGE;
    uint32_t s3 = sbase + 3 * SM_STAGE;

    {
        const __half* aS = g_xh + (size_t)(row0 + aRow) * Dd + aC0 * 8;
        const __half* bS = g_wh + (size_t)(k0 + bRow) * Dd + bC * 8;
        uint32_t st[3] = { s0, s1, s2 };
        #pragma unroll
        for (int p = 0; p < 3; p++) {
            cpasync16(st[p] + aDst, aS + p * BK);
            cpasync16(st[p] + aDst + 16, aS + p * BK + 8);
            cpasync16(st[p] + bDst, bS + p * BK);
            CP_COMMIT();
        }
    }
    if (tid < BN) wnsS[tid] = g_wn[k0 + tid];

    const __half* aPref = g_xh + (size_t)(row0 + aRow) * Dd + aC0 * 8 + 3 * BK;
    const __half* bPref = g_wh + (size_t)(k0 + bRow) * Dd + bC * 8 + 3 * BK;
    int pkt = 3, pch = 0;

    float best1[4], best2[4];
    int idx1[4];
    #pragma unroll
    for (int r = 0; r < 4; r++) { best1[r] = -3.4e38f; best2[r] = -3.4e38f; idx1[r] = 0; }

    for (int ch = 0; ch < NCHUNK; ch++) {
        float acc[2][4][4];
        #pragma unroll
        for (int i = 0; i < 2; i++)
            #pragma unroll
            for (int j = 0; j < 4; j++)
                #pragma unroll
                for (int q = 0; q < 4; q++) acc[i][j][q] = 0.0f;

        #pragma unroll
        for (int kt = 0; kt < 8; kt++) {
            CP_WAIT2();
            __syncthreads();

            if (kt == 0 && ch + 1 < NCHUNK && tid < BN)
                wnsS[((ch + 1) & 1) * BN + tid] = g_wn[k0 + (ch + 1) * BN + tid];

            cpasync16(s3 + aDst, aPref);
            cpasync16(s3 + aDst + 16, aPref + 8);
            cpasync16(s3 + bDst, bPref);
            CP_COMMIT();
            if (++pkt == 8) {
                pkt = 0;
                aPref -= 7 * BK;
                bPref += BN * Dd - 7 * BK;
                if (++pch == NCHUNK) { pch = 0; bPref -= (size_t)KSEG * Dd; }
            } else {
                aPref += BK;
                bPref += BK;
            }

            #pragma unroll
            for (int ks = 0; ks < 2; ks++) {
                uint32_t a[2][4];
                #pragma unroll
                for (int i = 0; i < 2; i++)
                    LDSM_X4(a[i][0], a[i][1], a[i][2], a[i][3],
                            s0 + laneA + (uint32_t)(i * 1280 + ks * 32));
                uint32_t b[4][2];
                LDSM_X4(b[0][0], b[0][1], b[1][0], b[1][1],
                        s0 + laneB + (uint32_t)(ks * 32));
                LDSM_X4(b[2][0], b[2][1], b[3][0], b[3][1],
                        s0 + laneB + (uint32_t)(1280 + ks * 32));
                #pragma unroll
                for (int i = 0; i < 2; i++)
                    #pragma unroll
                    for (int j = 0; j < 4; j++)
                        MMA16816(acc[i][j], a[i], b[j]);
            }

            uint32_t t = s0; s0 = s1; s1 = s2; s2 = s3; s3 = t;
        }

        const int kc = k0 + ch * BN;
        const float* wn = wnsS + (ch & 1) * BN;
        #pragma unroll
        for (int i = 0; i < 2; i++) {
            #pragma unroll
            for (int h = 0; h < 2; h++) {
                const int r = i * 2 + h;
                #pragma unroll
                for (int j = 0; j < 4; j++) {
                    int col = warp_n * 32 + j * 8 + (lane & 3) * 2;
                    #pragma unroll
                    for (int q = 0; q < 2; q++) {
                        float s = acc[i][j][h * 2 + q] - wn[col + q];
                        int k = kc + col + q;
                        if (s > best1[r]) { best2[r] = best1[r]; best1[r] = s; idx1[r] = k; }
                        else if (s > best2[r]) { best2[r] = s; }
                    }
                }
            }
        }
    }

    const int e = warp_n * 4 + (lane & 3);
    #pragma unroll
    for (int r = 0; r < 4; r++) {
        int row = warp_m * 32 + (r >> 1) * 16 + (lane >> 2) + (r & 1) * 8;
        mv1[row * 8 + e] = best1[r];
        mv2[row * 8 + e] = best2[r];
        mi[row * 8 + e] = idx1[r];
    }
    __syncthreads();

    if (tid < BM) {
        float b1 = -3.4e38f, b2 = -3.4e38f;
        int bi = 0;
        #pragma unroll
        for (int t = 0; t < 8; t++) {
            float v = mv1[tid * 8 + t];
            int ii = mi[tid * 8 + t];
            if (v > b1 || (v == b1 && ii < bi)) { b2 = (b2 > b1) ? b2 : b1; b1 = v; bi = ii; }
            else if (v > b2) b2 = v;
            float v2 = mv2[tid * 8 + t];
            if (v2 > b2) b2 = v2;
        }
        int n = row0 + tid;
        g_pb1[n * NSPLIT + split] = b1;
        g_pb2[n * NSPLIT + split] = b2;
        g_pidx[n * NSPLIT + split] = bi;
    }
}

// ---------------------------------------------------------------------------
// Merge: combine 8 splits, flag rows, build per-split heavy lists
// ---------------------------------------------------------------------------
__global__ void merge_kernel() {
    int n = blockIdx.x * 256 + threadIdx.x;
    float b1 = -3.4e38f, b2 = -3.4e38f;
    int bi = 0;
    #pragma unroll
    for (int s = 0; s < NSPLIT; s++) {
        float v = g_pb1[n * NSPLIT + s];
        int ii = g_pidx[n * NSPLIT + s];
        float v2 = g_pb2[n * NSPLIT + s];
        if (v > b1 || (v == b1 && ii < bi)) { b2 = (b2 > b1) ? b2 : b1; b1 = v; bi = ii; }
        else if (v > b2) b2 = v;
        if (v2 > b2) b2 = v2;
    }
    g_idx[n] = bi;

    const float thr = b1 - MARGIN;
    int nc = 0, hmask = 0;
    #pragma unroll
    for (int s = 0; s < NSPLIT; s++) {
        if (g_pb1[n * NSPLIT + s] >= thr) nc++;
        if (g_pb2[n * NSPLIT + s] >= thr) hmask |= (1 << s);
    }

    if (nc >= 2 || hmask) {
        g_res[n] = 0ull;
        unsigned slot = atomicAdd(&g_nf, 1u);
        if (slot < CAPF) g_flag[slot] = n;
        #pragma unroll
        for (int s = 0; s < NSPLIT; s++) {
            if (hmask & (1 << s)) {
                unsigned h = atomicAdd(&g_nhs[s], 1u);
                if (h < CAP_S) g_hlist[s * CAP_S + h] = n;
            }
        }
    }
}

// ---------------------------------------------------------------------------
// Candidate rescore: one warp per flagged row; exact fp32 of the 8 split-pidx.
// ---------------------------------------------------------------------------
__global__ void __launch_bounds__(256) cand_kernel(const float* __restrict__ X,
                                                   const float* __restrict__ W) {
    unsigned cnt = g_nf; if (cnt > CAPF) cnt = CAPF;
    unsigned r = blockIdx.x * 8 + (threadIdx.x >> 5);
    if (r >= cnt) return;
    const int lane = threadIdx.x & 31;
    const int n = (int)g_flag[r];

    const float4* xp = (const float4*)(X + (size_t)n * Dd);
    float4 x0 = xp[lane * 2];
    float4 x1 = xp[lane * 2 + 1];

    unsigned long long best = 0ull;
    #pragma unroll
    for (int s = 0; s < NSPLIT; s++) {
        int k = g_pidx[n * NSPLIT + s];
        const float4* wp = (const float4*)(W + (size_t)k * Dd);
        float4 w0 = wp[lane * 2];
        float4 w1 = wp[lane * 2 + 1];
        float dot = x0.x * w0.x + x0.y * w0.y + x0.z * w0.z + x0.w * w0.w
                  + x1.x * w1.x + x1.y * w1.y + x1.z * w1.z + x1.w * w1.w;
        #pragma unroll
        for (int o = 16; o > 0; o >>= 1) dot += __shfl_xor_sync(0xffffffffu, dot, o);
        unsigned long long key = pack_key(dot - g_wn[k], k);
        if (key > best) best = key;
    }
    if (lane == 0) atomicMax(&g_res[n], best);
}

// ---------------------------------------------------------------------------
// Heavy rescue: per (split of 8, 256-k subsegment of 4, rowgroup of 32).
// ---------------------------------------------------------------------------
#define WPITCH 260
#define RROWS 32
#define RS_XS 0
#define RS_WS (RROWS * 256 * 4)                 // 32768
#define RS_SMEM (RS_WS + 32 * WPITCH * 4)       // 66048 bytes

__global__ void __launch_bounds__(256) heavy_kernel(const float* __restrict__ X,
                                                    const float* __restrict__ W) {
    extern __shared__ char rsm[];
    float* xs = (float*)(rsm + RS_XS);
    float* ws = (float*)(rsm + RS_WS);

    const int bx = blockIdx.x;
    const int s = bx & 7;                          // split
    const int sub = (bx >> 3) & 3;                 // 256-k subsegment (KSEG/256 = 4)
    const unsigned grp = (unsigned)(bx >> 5);      // row group

    unsigned cnt = g_nhs[s]; if (cnt > CAP_S) cnt = CAP_S;
    if (grp * RROWS >= cnt) return;

    const int tid = threadIdx.x;
    const int w = tid >> 5;
    const int tx = tid & 31;
    const unsigned* list = g_hlist + s * CAP_S;

    #pragma unroll
    for (int q = 0; q < 8; q++) {
        int f = q * 256 + tid;
        int r = f >> 6, seg = f & 63;
        unsigned slot = grp * RROWS + r;
        int n = (int)list[slot < cnt ? slot : (grp * RROWS)];
        *(float4*)&xs[r * 256 + seg * 4] =
            ((const float4*)(X + (size_t)n * Dd))[seg];
    }

    unsigned long long key[4];
    #pragma unroll
    for (int i = 0; i < 4; i++) key[i] = 0ull;

    const int k0 = s * KSEG + sub * 256;
    for (int kc = 0; kc < 256; kc += 32) {
        __syncthreads();
        {
            const int kr = tid >> 3, seg = tid & 7;
            const float4* src = (const float4*)(W + (size_t)(k0 + kc + kr) * Dd);
            #pragma unroll
            for (int q = 0; q < 8; q++)
                *(float4*)&ws[kr * WPITCH + (seg * 8 + q) * 4] = src[seg * 8 + q];
        }
        __syncthreads();

        const int k = k0 + kc + tx;
        float dot[4];
        #pragma unroll
        for (int i = 0; i < 4; i++) dot[i] = 0.0f;
        #pragma unroll
        for (int d = 0; d < 256; d += 4) {
            float4 wv = *(const float4*)&ws[tx * WPITCH + d];
            #pragma unroll
            for (int i = 0; i < 4; i++) {
                float4 xv = *(const float4*)&xs[(w * 4 + i) * 256 + d];
                dot[i] += wv.x * xv.x + wv.y * xv.y + wv.z * xv.z + wv.w * xv.w;
            }
        }
        const float wn = g_wn[k];
        #pragma unroll
        for (int i = 0; i < 4; i++) {
            unsigned long long kk2 = pack_key(dot[i] - wn, k);
            if (kk2 > key[i]) key[i] = kk2;
        }
    }

    #pragma unroll
    for (int i = 0; i < 4; i++) {
        unsigned long long kv = key[i];
        #pragma unroll
        for (int o = 16; o > 0; o >>= 1) {
            unsigned long long other = __shfl_xor_sync(0xffffffffu, kv, o);
            if (other > kv) kv = other;
        }
        if (tx == 0) {
            unsigned slot = grp * RROWS + w * 4 + i;
            if (slot < cnt) atomicMax(&g_res[list[slot]], kv);
        }
    }
}

__global__ void apply_kernel() {
    unsigned cnt = g_nf; if (cnt > CAPF) cnt = CAPF;
    unsigned t = blockIdx.x * 256 + threadIdx.x;
    if (t < cnt) {
        int n = (int)g_flag[t];
        unsigned long long key = g_res[n];
        g_idx[n] = (int)(0xFFFFFFFFu - (unsigned)(key & 0xFFFFFFFFull));
    }
}

// ---------------------------------------------------------------------------
// Gather: 8 rows per block
// ---------------------------------------------------------------------------
__global__ void gather_kernel(const float* __restrict__ W,
                              float* __restrict__ outq,
                              float* __restrict__ outi,
                              int write_idx) {
    int n = blockIdx.x * 8 + (threadIdx.x >> 5);
    int lane = threadIdx.x & 31;
    int idx = g_idx[n];
    const float4* src = (const float4*)(W + (size_t)idx * Dd);
    float4* dst = (float4*)(outq + (size_t)n * Dd);
    dst[lane] = src[lane];
    dst[lane + 32] = src[lane + 32];
    if (lane == 0 && write_idx) outi[n] = (float)idx;
}

// ---------------------------------------------------------------------------
extern "C" void kernel_launch(void* const* d_in, const int* in_sizes, int n_in,
                              void* d_out, int out_size) {
    const float* X = (const float*)d_in[0];
    const float* W = (const float*)d_in[1];
    float* out = (float*)d_out;

    cudaFuncSetAttribute(stage1_kernel,
                         cudaFuncAttributeMaxDynamicSharedMemorySize, SMEM_TOTAL);
    cudaFuncSetAttribute(heavy_kernel,
                         cudaFuncAttributeMaxDynamicSharedMemorySize, RS_SMEM);

    prep_kernel<<<CVX_BLKS + CVW_BLKS + WN_BLKS, 256>>>(X, W);

    stage1_kernel<<<(Nn / BM) * NSPLIT, 256, SMEM_TOTAL>>>();
    merge_kernel<<<Nn / 256, 256>>>();

    cand_kernel<<<CAPF / 8, 256>>>(X, W);
    heavy_kernel<<<NSPLIT * 4 * (CAP_S / RROWS), 256, RS_SMEM>>>(X, W);
    apply_kernel<<<(CAPF + 255) / 256, 256>>>();

    int write_idx = (out_size >= Nn * Dd + Nn) ? 1 : 0;
    gather_kernel<<<Nn / 8, 256>>>(W, out, out + (size_t)Nn * Dd, write_idx);
}